// round 10
// baseline (speedup 1.0000x reference)
#include <cuda_runtime.h>
#include <cuda_bf16.h>
#include <cstdint>
#include <math.h>

// B=32, T=500, E=1024, D=1024, EMB=256, O=5000, olen=100, A=512
#define NBLK   148
#define NTHR   512
#define NUNITS 296     // 2 tile units per block

// ---------------- scratch layout (floats) ----------------
#define OFF_EYS   ((size_t)0)          // (100,32,256)
#define OFF_SB    ((size_t)819200)     // (100,32,2048)
#define OFF_SBX   ((size_t)7372800)    // (100,32,1024)
#define OFF_ENC   ((size_t)10649600)   // (32,500,512)
#define OFF_HSUM  ((size_t)18841600)
#define OFF_H     ((size_t)18874368)
#define OFF_H1    ((size_t)18907136)
#define OFF_C     ((size_t)18939904)
#define OFF_EN    ((size_t)18972672)   // (32,500)
#define OFF_YM    ((size_t)18988672)   // (100,32)
#define OFF_L512  ((size_t)18991872)   // (32,512)
#define OFF_MS    ((size_t)19008256)   // (32,8,2)
#define OFF_EXP   ((size_t)19008768)   // (32,5000)
#define OFF_PA    ((size_t)19168768)   // 24*131072 = 3,145,728
#define OFF_PB    ((size_t)22314496)   // 72*32768  = 2,359,296
#define SZ_TOTAL  ((size_t)24673792)

__device__ float g_scratch[SZ_TOTAL];
__device__ unsigned g_bar_cnt;

// ---------------- grid barrier: REDG arrive + acquire poll ----------------
__device__ __forceinline__ void gsync(unsigned& gen) {
    gen += NBLK;
    __syncthreads();
    if (threadIdx.x == 0) {
        asm volatile("red.release.gpu.global.add.u32 [%0], 1;"
                     :: "l"(&g_bar_cnt) : "memory");
        unsigned v;
        while (true) {
            asm volatile("ld.acquire.gpu.global.u32 %0, [%1];"
                         : "=r"(v) : "l"(&g_bar_cnt) : "memory");
            if ((int)(v - gen) >= 0) break;
            __nanosleep(32);
        }
    }
    __syncthreads();
}

// unit-local barrier (256 threads, barrier id 1 or 2)
__device__ __forceinline__ void usync(int unit) {
    asm volatile("bar.sync %0, 256;" :: "r"(unit + 1) : "memory");
}

__device__ __forceinline__ float sigm(float x) { return 1.f / (1.f + expf(-x)); }

// ---------------- GEMM building blocks (32 rows x 256 cols tile, per unit) ----
__device__ __forceinline__ void load_A(const float* A, int ldA, int k0, float* sAT) {
    int utid = threadIdx.x & 255;
    int r = utid & 31, q = utid >> 5;
    float4 v = *(const float4*)(A + (size_t)r * ldA + k0 + q * 4);
    sAT[(q*4+0)*32 + r] = v.x; sAT[(q*4+1)*32 + r] = v.y;
    sAT[(q*4+2)*32 + r] = v.z; sAT[(q*4+3)*32 + r] = v.w;
}

__device__ __forceinline__ void load_W_sync(const float* W, int ldW, int k0,
                                            int colBase, int ncols, float* sW) {
    int utid = threadIdx.x & 255;
    #pragma unroll
    for (int v8 = 0; v8 < 8; v8++) {
        int id = utid + v8 * 256;
        int kr = id >> 6;
        int c4 = (id & 63) << 2;
        const float* src = W + (size_t)(k0 + kr) * ldW + colBase + c4;
        float4 val;
        if (c4 + 4 <= ncols) {
            val = *(const float4*)src;
        } else {
            val.x = (c4 + 0 < ncols) ? src[0] : 0.f;
            val.y = (c4 + 1 < ncols) ? src[1] : 0.f;
            val.z = (c4 + 2 < ncols) ? src[2] : 0.f;
            val.w = (c4 + 3 < ncols) ? src[3] : 0.f;
        }
        *(float4*)(sW + kr * 256 + c4) = val;
    }
}

__device__ __forceinline__ void load_W_async(const float* W, int ldW, int k0,
                                             int colBase, int ncols, float* sWdst) {
    unsigned sbase = (unsigned)__cvta_generic_to_shared(sWdst);
    int utid = threadIdx.x & 255;
    #pragma unroll
    for (int v8 = 0; v8 < 8; v8++) {
        int id = utid + v8 * 256;
        int kr = id >> 6;
        int c4 = (id & 63) << 2;
        int rem = ncols - c4;
        int sz = rem >= 4 ? 16 : (rem > 0 ? rem * 4 : 0);
        int cc = (sz > 0) ? c4 : 0;
        const float* src = W + (size_t)(k0 + kr) * ldW + colBase + cc;
        unsigned d = sbase + (unsigned)((kr * 256 + c4) * 4);
        asm volatile("cp.async.cg.shared.global [%0], [%1], 16, %2;"
                     :: "r"(d), "l"(src), "r"(sz));
    }
}

// packed f32x2 MMA: acc[i][j] holds rows (rt*8+2i, rt*8+2i+1), col ct*4+j
__device__ __forceinline__ void mma_chunk(unsigned long long acc[4][4],
                                          const float* sAT, const float* sW) {
    int utid = threadIdx.x & 255;
    int ct = utid & 63, rt = utid >> 6;
    #pragma unroll
    for (int kk = 0; kk < 32; kk++) {
        const unsigned long long* ap =
            (const unsigned long long*)(sAT + kk * 32 + rt * 8);
        unsigned long long a0 = ap[0], a1 = ap[1], a2 = ap[2], a3 = ap[3];
        float4 w = *(const float4*)(sW + kk * 256 + ct * 4);
        unsigned long long w0, w1, w2, w3;
        asm("mov.b64 %0, {%1,%1};" : "=l"(w0) : "f"(w.x));
        asm("mov.b64 %0, {%1,%1};" : "=l"(w1) : "f"(w.y));
        asm("mov.b64 %0, {%1,%1};" : "=l"(w2) : "f"(w.z));
        asm("mov.b64 %0, {%1,%1};" : "=l"(w3) : "f"(w.w));
        #define F2X(ac, av, wv) \
            asm("fma.rn.f32x2 %0, %1, %2, %0;" : "+l"(ac) : "l"(av), "l"(wv));
        F2X(acc[0][0], a0, w0) F2X(acc[0][1], a0, w1)
        F2X(acc[0][2], a0, w2) F2X(acc[0][3], a0, w3)
        F2X(acc[1][0], a1, w0) F2X(acc[1][1], a1, w1)
        F2X(acc[1][2], a1, w2) F2X(acc[1][3], a1, w3)
        F2X(acc[2][0], a2, w0) F2X(acc[2][1], a2, w1)
        F2X(acc[2][2], a2, w2) F2X(acc[2][3], a2, w3)
        F2X(acc[3][0], a3, w0) F2X(acc[3][1], a3, w1)
        F2X(acc[3][2], a3, w2) F2X(acc[3][3], a3, w3)
        #undef F2X
    }
}

__device__ __forceinline__ void store_tile(unsigned long long acc[4][4],
                                           float* outBase, int Ntot, int ncols) {
    int utid = threadIdx.x & 255;
    int ct = utid & 63, rt = utid >> 6;
    int c = ct * 4;
    #pragma unroll
    for (int i = 0; i < 4; i++) {
        float lo[4], hi[4];
        #pragma unroll
        for (int j = 0; j < 4; j++)
            asm("mov.b64 {%0,%1}, %2;" : "=f"(lo[j]), "=f"(hi[j]) : "l"(acc[i][j]));
        float* d0 = outBase + (size_t)(rt * 8 + 2 * i) * Ntot + c;
        float* d1 = outBase + (size_t)(rt * 8 + 2 * i + 1) * Ntot + c;
        if (c + 4 <= ncols) {
            *(float4*)d0 = make_float4(lo[0], lo[1], lo[2], lo[3]);
            *(float4*)d1 = make_float4(hi[0], hi[1], hi[2], hi[3]);
        } else {
            #pragma unroll
            for (int q = 0; q < 4; q++)
                if (c + q < ncols) { d0[q] = lo[q]; d1[q] = hi[q]; }
        }
    }
}

struct GPair { const float* A; int ldA; const float* W; int ldW; int K; };

// double-buffered pipelined tile: cp.async W(i+1) overlaps compute(i)
__device__ void gemm_tile(const GPair* pr, int np, int ks, int KS,
                          int colBase, int ncols, float* outSlot, int Ntot,
                          float* abuf, float* wbuf, int unit) {
    unsigned long long acc[4][4] = {};
    int pidx[8], koff[8];
    int m = 0, gc = 0;
    for (int p = 0; p < np; p++)
        for (int k0 = 0; k0 < pr[p].K; k0 += 32)
            if ((gc++ % KS) == ks) { pidx[m] = p; koff[m] = k0; m++; }

    if (m > 0) {
        load_W_async(pr[pidx[0]].W, pr[pidx[0]].ldW, koff[0], colBase, ncols, wbuf);
        asm volatile("cp.async.commit_group;" ::: "memory");
        load_A(pr[pidx[0]].A, pr[pidx[0]].ldA, koff[0], abuf);
    }
    for (int i = 0; i < m; i++) {
        asm volatile("cp.async.wait_group 0;" ::: "memory");
        usync(unit);
        if (i + 1 < m) {
            load_W_async(pr[pidx[i+1]].W, pr[pidx[i+1]].ldW, koff[i+1],
                         colBase, ncols, wbuf + ((i + 1) & 1) * 8192);
            asm volatile("cp.async.commit_group;" ::: "memory");
            load_A(pr[pidx[i+1]].A, pr[pidx[i+1]].ldA, koff[i+1],
                   abuf + ((i + 1) & 1) * 1024);
        }
        mma_chunk(acc, abuf + (i & 1) * 1024, wbuf + (i & 1) * 8192);
        usync(unit);
    }
    store_tile(acc, outSlot, Ntot, ncols);
}

// ---------------- megakernel ----------------
struct MKArgs {
    const float *hs, *U1, *Ux1, *U2, *b2, *Wc, *Ux2, *bUx2, *Wcx;
    const float *Ws, *bs, *Wy, *We, *Wlogit, *blogit, *Wdec, *Winit, *binit;
    const int* hlens;
    float* out;
};

__global__ void __launch_bounds__(NTHR, 1) k_mega(MKArgs a) {
    extern __shared__ float SM[];
    const int unit = threadIdx.x >> 8;     // 0 or 1
    const int utid = threadIdx.x & 255;
    const int ug   = blockIdx.x * 2 + unit;  // 0..295
    float* USM  = SM + unit * 18432;       // per-unit 73728 bytes
    float* abuf = USM;                     // 2048 floats (2 x 32x32)
    float* wbuf = USM + 2048;              // 16384 floats (2 x 32x256)

    float* eys  = g_scratch + OFF_EYS;
    float* sb   = g_scratch + OFF_SB;
    float* sbx  = g_scratch + OFF_SBX;
    float* enc  = g_scratch + OFF_ENC;
    float* hsum = g_scratch + OFF_HSUM;
    float* h    = g_scratch + OFF_H;
    float* h1   = g_scratch + OFF_H1;
    float* cvec = g_scratch + OFF_C;
    float* en   = g_scratch + OFF_EN;
    float* ym   = g_scratch + OFF_YM;
    float* l512 = g_scratch + OFF_L512;
    float* ms   = g_scratch + OFF_MS;
    float* expb = g_scratch + OFF_EXP;
    float* pA   = g_scratch + OFF_PA;
    float* pB   = g_scratch + OFF_PB;

    unsigned gen = 0;

    // ===== h0 = hsum @ Winit + binit : 128 tiles (4 ct x 32 ks) =====
    for (int t = ug; t < 128; t += NUNITS) {
        int ct = t & 3, ks = t >> 2;
        GPair p = {hsum, 1024, a.Winit, 1024, 1024};
        gemm_tile(&p, 1, ks, 32, ct * 256, 256,
                  pA + (size_t)ks * 32768 + ct * 256, 1024, abuf, wbuf, unit);
    }
    gsync(gen);
    for (int idx = blockIdx.x * NTHR + threadIdx.x; idx < 32768; idx += NBLK * NTHR) {
        float s = a.binit[idx & 1023];
        for (int sI = 0; sI < 32; sI++) s += pA[(size_t)sI * 32768 + idx];
        h[idx] = s;
    }
    gsync(gen);

    for (int step = 0; step < 100; step++) {
        // ===== phase 1: fused 9b(step-1) + gate1 = [h@U1 | h@Ux1], 288 tiles =====
        if (step > 0) {
            for (int t = ug; t < 256; t += NUNITS) {
                int b = t & 31, q = t >> 5;
                float gm = -1e30f;
                #pragma unroll
                for (int w = 0; w < 8; w++) gm = fmaxf(gm, ms[(b * 8 + w) * 2]);
                float gs = 0.f;
                #pragma unroll
                for (int w = 0; w < 8; w++)
                    gs += ms[(b * 8 + w) * 2 + 1] * expf(ms[(b * 8 + w) * 2] - gm);
                float scale = expf(ms[(b * 8 + q) * 2] - gm) / gs;
                float* o = a.out + (size_t)b * 500000 + (size_t)(step - 1) * 5000 + q * 625;
                const float* src = expb + (size_t)b * 5000 + q * 625;
                for (int j0 = utid; j0 < 625; j0 += 256) o[j0] = src[j0] * scale;
            }
        }
        for (int t = ug; t < 288; t += NUNITS) {
            int ct = t % 12, ks = t / 12;      // KS=24
            if (ct < 8) {
                GPair p = {h, 1024, a.U1, 2048, 1024};
                gemm_tile(&p, 1, ks, 24, ct * 256, 256,
                          pA + (size_t)ks * 98304 + ct * 256, 3072, abuf, wbuf, unit);
            } else {
                GPair p = {h, 1024, a.Ux1, 1024, 1024};
                gemm_tile(&p, 1, ks, 24, (ct - 8) * 256, 256,
                          pA + (size_t)ks * 98304 + 2048 + (ct - 8) * 256, 3072,
                          abuf, wbuf, unit);
            }
        }
        gsync(gen);

        // ===== phase 2: ew1 (fused 24-slot reduce) + dq GEMM chunk, 64 tiles =====
        for (int t = ug; t < 64; t += NUNITS) {
            int ct = t & 1, ks = t >> 1;       // chunk = ks (0..31)
            usync(unit);
            #pragma unroll
            for (int v = 0; v < 4; v++) {
                int idx = utid + v * 256;
                int r = idx >> 5, jj = idx & 31;
                int j = ks * 32 + jj;
                float prv = 0.f, uv = 0.f, hx = 0.f;
                #pragma unroll
                for (int s = 0; s < 24; s++) {
                    const float* P = pA + (size_t)s * 98304 + (size_t)r * 3072;
                    prv += P[j]; uv += P[1024 + j]; hx += P[2048 + j];
                }
                const float* x_ = sb + (size_t)step * 65536 + (size_t)r * 2048;
                prv = sigm(prv + x_[j]);
                uv  = sigm(uv + x_[1024 + j]);
                float ht = tanhf(hx * prv + sbx[(size_t)step * 32768 + r * 1024 + j]);
                float hold = h[r * 1024 + j];
                float m = ym[step * 32 + r];
                float h1v = m * (uv * hold + (1.f - uv) * ht) + (1.f - m) * hold;
                abuf[jj * 32 + r] = h1v;
                if (ct == 0) h1[r * 1024 + j] = h1v;
            }
            load_W_sync(a.Wdec, 512, ks * 32, ct * 256, 256, wbuf);
            usync(unit);
            unsigned long long acc[4][4] = {};
            mma_chunk(acc, abuf, wbuf);
            usync(unit);
            store_tile(acc, pB + (size_t)ks * 16384 + ct * 256, 512, 256);
        }
        gsync(gen);

        // ===== phase 3: attention scores en[b,t], 256 tiles =====
        for (int t = ug; t < 256; t += NUNITS) {
            int b = t & 31, tch = t >> 5;      // 8 chunks of 63
            usync(unit);
            float* dqs = USM;
            for (int j = utid; j < 512; j += 256) {
                float s = 0.f;
                #pragma unroll 8
                for (int sI = 0; sI < 32; sI++)
                    s += pB[(size_t)sI * 16384 + b * 512 + j];
                dqs[j] = tanhf(s);
            }
            usync(unit);
            int w = utid >> 5, l = utid & 31;
            int hl = a.hlens[b];
            int tend = tch * 63 + 63; if (tend > 500) tend = 500;
            for (int tt = tch * 63 + w; tt < tend; tt += 8) {
                const float* row = enc + ((size_t)b * 500 + tt) * 512;
                float s = 0.f;
                #pragma unroll
                for (int q = 0; q < 16; q++)
                    s = fmaf(row[l + q * 32], dqs[l + q * 32], s);
                #pragma unroll
                for (int o = 16; o; o >>= 1) s += __shfl_xor_sync(0xffffffffu, s, o);
                if (l == 0) en[b * 500 + tt] = (tt < hl) ? s : -1e9f;
            }
            usync(unit);
        }
        gsync(gen);

        // ===== phase 4: softmax(en) + context c, 256 tiles (b x 8 e-chunks) =====
        for (int t = ug; t < 256; t += NUNITS) {
            int b = t & 31, ech = t >> 5;      // e range [ech*128, +128)
            float* ws  = USM;                  // 500 exps
            float* red = USM + 512;            // 8
            float* cp  = USM + 528;            // 256 ctx partials
            usync(unit);
            float v0 = (utid < 500) ? en[b * 500 + utid] : -1e30f;
            float v1 = (utid + 256 < 500) ? en[b * 500 + utid + 256] : -1e30f;
            float lm = fmaxf(v0, v1);
            #pragma unroll
            for (int o = 16; o; o >>= 1) lm = fmaxf(lm, __shfl_xor_sync(0xffffffffu, lm, o));
            if ((utid & 31) == 0) red[utid >> 5] = lm;
            usync(unit);
            float gm = red[0];
            #pragma unroll
            for (int w = 1; w < 8; w++) gm = fmaxf(gm, red[w]);
            float e0 = (utid < 500) ? expf(v0 - gm) : 0.f;
            float e1 = (utid + 256 < 500) ? expf(v1 - gm) : 0.f;
            if (utid < 500) ws[utid] = e0;
            if (utid + 256 < 500) ws[utid + 256] = e1;
            float ls = e0 + e1;
            #pragma unroll
            for (int o = 16; o; o >>= 1) ls += __shfl_xor_sync(0xffffffffu, ls, o);
            usync(unit);
            if ((utid & 31) == 0) red[utid >> 5] = ls;
            usync(unit);
            float tot = 0.f;
            #pragma unroll
            for (int w = 0; w < 8; w++) tot += red[w];
            float inv = 1.f / tot;
            // context: 128 e-cols, 2 t-halves of 250
            int e = ech * 128 + (utid & 127);
            int th = utid >> 7;
            const float* base = a.hs + (size_t)b * 512000 + e + (size_t)th * 250 * 1024;
            const float* wsb = ws + th * 250;
            float s0 = 0.f, s1 = 0.f;
            #pragma unroll 2
            for (int t4 = 0; t4 < 250; t4 += 2) {
                s0 = fmaf(wsb[t4],     base[(size_t)t4 * 1024], s0);
                s1 = fmaf(wsb[t4 + 1], base[(size_t)(t4 + 1) * 1024], s1);
            }
            cp[utid] = s0 + s1;
            usync(unit);
            if (utid < 128)
                cvec[b * 1024 + e] = (cp[utid] + cp[utid + 128]) * inv;
            usync(unit);
        }
        gsync(gen);

        // ===== phase 5: gate2 = [h1@U2+c@Wc | h1@Ux2 | c@Wcx], 288 tiles =====
        for (int t = ug; t < 288; t += NUNITS) {
            if (t < 192) {
                int ct = t % 8, ks = t / 8;       // KS=24, 64 chunks (2 pairs)
                GPair p2[2] = {{h1, 1024, a.U2, 2048, 1024},
                               {cvec, 1024, a.Wc, 2048, 1024}};
                gemm_tile(p2, 2, ks, 24, ct * 256, 256,
                          pA + (size_t)ks * 131072 + ct * 256, 4096, abuf, wbuf, unit);
            } else if (t < 240) {
                int tt = t - 192, ct = tt % 4, ks = tt / 4;  // KS=12
                GPair p = {h1, 1024, a.Ux2, 1024, 1024};
                gemm_tile(&p, 1, ks, 12, ct * 256, 256,
                          pA + (size_t)ks * 131072 + 2048 + ct * 256, 4096, abuf, wbuf, unit);
            } else {
                int tt = t - 240, ct = tt % 4, ks = tt / 4;  // KS=12
                GPair p = {cvec, 1024, a.Wcx, 1024, 1024};
                gemm_tile(&p, 1, ks, 12, ct * 256, 256,
                          pA + (size_t)ks * 131072 + 3072 + ct * 256, 4096, abuf, wbuf, unit);
            }
        }
        gsync(gen);

        // ===== phase 6: ew2 (fused) + logit GEMM, 288 one-chunk tiles =====
        for (int t = ug; t < 288; t += NUNITS) {
            int ct = t & 3, c = t >> 2;         // chunk id 0..71
            usync(unit);
            if (c < 32) {
                #pragma unroll
                for (int v = 0; v < 4; v++) {
                    int idx = utid + v * 256;
                    int r = idx >> 5, jj = idx & 31;
                    int j = c * 32 + jj;
                    float prv = 0.f, uv = 0.f, hx = 0.f, cx = 0.f;
                    #pragma unroll
                    for (int s = 0; s < 24; s++) {
                        const float* P = pA + (size_t)s * 131072 + (size_t)r * 4096;
                        prv += P[j]; uv += P[1024 + j];
                    }
                    #pragma unroll
                    for (int s = 0; s < 12; s++) {
                        const float* P = pA + (size_t)s * 131072 + (size_t)r * 4096;
                        hx += P[2048 + j]; cx += P[3072 + j];
                    }
                    prv = sigm(prv + a.b2[j]);
                    uv  = sigm(uv + a.b2[1024 + j]);
                    float ht = tanhf((hx + a.bUx2[j]) * prv + cx);
                    float h1v = h1[r * 1024 + j];
                    float m = ym[step * 32 + r];
                    float h2v = m * (uv * h1v + (1.f - uv) * ht) + (1.f - m) * h1v;
                    abuf[jj * 32 + r] = h2v;
                    if (ct == 0) h[r * 1024 + j] = h2v;
                }
                load_W_sync(a.Ws, 1024, c * 32, ct * 256, 256, wbuf);
            } else if (c < 40) {
                load_A(eys + (size_t)step * 8192, 256, (c - 32) * 32, abuf);
                load_W_sync(a.Wy, 1024, (c - 32) * 32, ct * 256, 256, wbuf);
            } else {
                load_A(cvec, 1024, (c - 40) * 32, abuf);
                load_W_sync(a.We, 1024, (c - 40) * 32, ct * 256, 256, wbuf);
            }
            usync(unit);
            unsigned long long acc[4][4] = {};
            mma_chunk(acc, abuf, wbuf);
            usync(unit);
            store_tile(acc, pB + (size_t)c * 32768 + ct * 256, 1024, 256);
        }
        gsync(gen);

        // ===== phase 7: pool (sum 72 slots + bias, pairwise max) -> l512 =====
        for (int idx = blockIdx.x * NTHR + threadIdx.x; idx < 16384; idx += NBLK * NTHR) {
            int r = idx >> 9, p2 = idx & 511;
            float v0 = a.bs[2 * p2], v1 = a.bs[2 * p2 + 1];
            #pragma unroll 8
            for (int s = 0; s < 72; s++) {
                const float* P = pB + (size_t)s * 32768 + (size_t)r * 1024;
                v0 += P[2 * p2]; v1 += P[2 * p2 + 1];
            }
            l512[idx] = fmaxf(v0, v1);
        }
        gsync(gen);

        // ===== phase 8: logits5000 = l512 @ Wlogit, 280 tiles (20 ct x 14 ks) =====
        for (int t = ug; t < 280; t += NUNITS) {
            int ct = t % 20, ks = t / 20;        // KS=14, 16 chunks
            int ncols = 5000 - ct * 256; if (ncols > 256) ncols = 256;
            GPair p = {l512, 512, a.Wlogit, 5000, 512};
            gemm_tile(&p, 1, ks, 14, ct * 256, ncols,
                      pA + (size_t)ks * 160000 + ct * 256, 5000, abuf, wbuf, unit);
        }
        gsync(gen);

        // ===== phase 9a: reduce 14 partials + local max + exp, 256 tiles =====
        for (int t = ug; t < 256; t += NUNITS) {
            int b = t & 31, q = t >> 5;          // cols [q*625, q*625+625)
            float* buf = USM;                    // 625
            float* red = USM + 640;              // 8
            usync(unit);
            float lm = -1e30f;
            for (int j0 = utid; j0 < 625; j0 += 256) {
                int j = q * 625 + j0;
                float v = a.blogit[j];
                #pragma unroll
                for (int s = 0; s < 14; s++)
                    v += pA[(size_t)s * 160000 + (size_t)b * 5000 + j];
                buf[j0] = v;
                lm = fmaxf(lm, v);
            }
            #pragma unroll
            for (int o = 16; o; o >>= 1) lm = fmaxf(lm, __shfl_xor_sync(0xffffffffu, lm, o));
            if ((utid & 31) == 0) red[utid >> 5] = lm;
            usync(unit);
            float gml = red[0];
            #pragma unroll
            for (int w = 1; w < 8; w++) gml = fmaxf(gml, red[w]);
            float ls = 0.f;
            for (int j0 = utid; j0 < 625; j0 += 256) {
                float e = expf(buf[j0] - gml);
                expb[(size_t)b * 5000 + q * 625 + j0] = e;
                ls += e;
            }
            #pragma unroll
            for (int o = 16; o; o >>= 1) ls += __shfl_xor_sync(0xffffffffu, ls, o);
            usync(unit);
            if ((utid & 31) == 0) red[utid >> 5] = ls;
            usync(unit);
            if (utid == 0) {
                float tot = 0.f;
                #pragma unroll
                for (int w = 0; w < 8; w++) tot += red[w];
                ms[(b * 8 + q) * 2]     = gml;
                ms[(b * 8 + q) * 2 + 1] = tot;
            }
            usync(unit);
        }
        gsync(gen);
    }

    // ===== final 9b for step 99 =====
    for (int t = ug; t < 256; t += NUNITS) {
        int b = t & 31, q = t >> 5;
        float gm = -1e30f;
        #pragma unroll
        for (int w = 0; w < 8; w++) gm = fmaxf(gm, ms[(b * 8 + w) * 2]);
        float gs = 0.f;
        #pragma unroll
        for (int w = 0; w < 8; w++)
            gs += ms[(b * 8 + w) * 2 + 1] * expf(ms[(b * 8 + w) * 2] - gm);
        float scale = expf(ms[(b * 8 + q) * 2] - gm) / gs;
        float* o = a.out + (size_t)b * 500000 + (size_t)99 * 5000 + q * 625;
        const float* src = expb + (size_t)b * 5000 + q * 625;
        for (int j0 = utid; j0 < 625; j0 += 256) o[j0] = src[j0] * scale;
    }
}

// ---------------- precompute: ONE setup kernel ----------------
__global__ void __launch_bounds__(128) k_setup(const int* __restrict__ ys,
                                               const float* __restrict__ embed,
                                               const float* __restrict__ hs,
                                               const int* __restrict__ hlens) {
    int bx = blockIdx.x;
    if (bx < 3200) {
        // eys gather: block = i*32 + b
        int i = bx >> 5, b = bx & 31;
        int tok = 4999;
        if (i > 0) { int v = ys[b * 99 + i - 1]; tok = (v < 0) ? 4999 : v; }
        float* ey = g_scratch + OFF_EYS + (size_t)bx * 256;
        const float* em = embed + (size_t)tok * 256;
        ((float2*)ey)[threadIdx.x] = ((const float2*)em)[threadIdx.x];
    } else if (bx == 3200) {
        if (threadIdx.x == 0) g_bar_cnt = 0;
        if (threadIdx.x < 32) {
            int b = threadIdx.x;
            int yl = 0;
            for (int j = 0; j < 99; j++) yl += (ys[b * 99 + j] != -1) ? 1 : 0;
            for (int i = 0; i < 100; i++)
                g_scratch[OFF_YM + i * 32 + b] = (i < yl + 1) ? 1.f : 0.f;
        }
    } else {
        // hsum: 256 blocks, block id = (bx-3201) = b*8 + echunk
        int id = bx - 3201;
        int b = id >> 3;
        int e = (id & 7) * 128 + threadIdx.x;
        const float* base = hs + (size_t)b * 512000 + e;
        float s0 = 0.f, s1 = 0.f, s2 = 0.f, s3 = 0.f;
        for (int t = 0; t < 500; t += 4) {
            s0 += base[(size_t)t * 1024];
            s1 += base[(size_t)(t + 1) * 1024];
            s2 += base[(size_t)(t + 2) * 1024];
            s3 += base[(size_t)(t + 3) * 1024];
        }
        g_scratch[OFF_HSUM + b * 1024 + e] = (s0 + s1 + s2 + s3) / (float)hlens[b];
    }
}

// ---------------- precompute: ONE tiled-GEMM kernel (3 regions) ----------------
__global__ void __launch_bounds__(256) k_tiled_all(const float* __restrict__ W1_W,
                                                   const float* __restrict__ b1_W,
                                                   const float* __restrict__ W1_Wx,
                                                   const float* __restrict__ b1_Wx,
                                                   const float* __restrict__ hs,
                                                   const float* __restrict__ Wenc) {
    const float* A; const float* W; const float* bias; float* C;
    int N, K, act, cx, cy;
    int bx = blockIdx.x;
    if (bx < 1600) {            // sb = eys @ W1_W + b1_W : (3200,2048)
        A = g_scratch + OFF_EYS; W = W1_W; bias = b1_W;
        C = g_scratch + OFF_SB; N = 2048; K = 256; act = 0;
        cx = bx % 32; cy = bx / 32;
    } else if (bx < 2400) {     // sbx = eys @ W1_Wx + b1_Wx : (3200,1024)
        int b2 = bx - 1600;
        A = g_scratch + OFF_EYS; W = W1_Wx; bias = b1_Wx;
        C = g_scratch + OFF_SBX; N = 1024; K = 256; act = 0;
        cx = b2 % 16; cy = b2 / 16;
    } else {                    // enc = tanh(hs @ Wenc) : (16000,512)
        int b2 = bx - 2400;
        A = hs; W = Wenc; bias = nullptr;
        C = g_scratch + OFF_ENC; N = 512; K = 1024; act = 1;
        cx = b2 % 8; cy = b2 / 8;
    }

    __shared__ float sAT[16][68];
    __shared__ float sWt[16][64];
    int rowBase = cy << 6;
    int colBase = cx << 6;
    int tx = threadIdx.x & 15;
    int ty = threadIdx.x >> 4;
    float acc[4][4];
    #pragma unroll
    for (int i = 0; i < 4; i++)
        #pragma unroll
        for (int j = 0; j < 4; j++) acc[i][j] = 0.f;

    for (int k0 = 0; k0 < K; k0 += 16) {
        __syncthreads();
        {
            int r = threadIdx.x >> 2;
            int c4 = (threadIdx.x & 3) << 2;
            float4 v = *(const float4*)(A + (size_t)(rowBase + r) * K + k0 + c4);
            sAT[c4+0][r] = v.x; sAT[c4+1][r] = v.y;
            sAT[c4+2][r] = v.z; sAT[c4+3][r] = v.w;
            int kr = threadIdx.x >> 4;
            int wc = (threadIdx.x & 15) << 2;
            *(float4*)&sWt[kr][wc] = *(const float4*)(W + (size_t)(k0 + kr) * N + colBase + wc);
        }
        __syncthreads();
        #pragma unroll
        for (int kk = 0; kk < 16; kk++) {
            float4 a4 = *(const float4*)&sAT[kk][ty << 2];
            float4 w4 = *(const float4*)&sWt[kk][tx << 2];
            float av[4] = {a4.x, a4.y, a4.z, a4.w};
            float wv[4] = {w4.x, w4.y, w4.z, w4.w};
            #pragma unroll
            for (int i = 0; i < 4; i++)
                #pragma unroll
                for (int j = 0; j < 4; j++)
                    acc[i][j] = fmaf(av[i], wv[j], acc[i][j]);
        }
    }
    #pragma unroll
    for (int i = 0; i < 4; i++) {
        int r = rowBase + (ty << 2) + i;
        #pragma unroll
        for (int j = 0; j < 4; j++) {
            int c = colBase + (tx << 2) + j;
            float v = acc[i][j];
            if (bias) v += bias[c];
            if (act == 1) v = tanhf(v);
            C[(size_t)r * N + c] = v;
        }
    }
}

// ---------------- host launcher ----------------
extern "C" void kernel_launch(void* const* d_in, const int* in_sizes, int n_in,
                              void* d_out, int out_size) {
    const float* hs     = (const float*)d_in[0];
    const int*   hlens  = (const int*)  d_in[1];
    const int*   ys     = (const int*)  d_in[2];
    const float* embed  = (const float*)d_in[3];
    const float* W1_W   = (const float*)d_in[4];
    const float* b1_W   = (const float*)d_in[5];
    const float* W1_Wx  = (const float*)d_in[6];
    const float* b1_Wx  = (const float*)d_in[7];
    const float* U1     = (const float*)d_in[8];
    const float* Ux1    = (const float*)d_in[9];
    const float* U2     = (const float*)d_in[10];
    const float* b2     = (const float*)d_in[11];
    const float* Wc     = (const float*)d_in[12];
    const float* Ux2    = (const float*)d_in[13];
    const float* bUx2   = (const float*)d_in[14];
    const float* Wcx    = (const float*)d_in[15];
    const float* Winit  = (const float*)d_in[16];
    const float* binit  = (const float*)d_in[17];
    const float* Ws     = (const float*)d_in[18];
    const float* bs     = (const float*)d_in[19];
    const float* Wy     = (const float*)d_in[20];
    const float* We     = (const float*)d_in[21];
    const float* Wlogit = (const float*)d_in[22];
    const float* blogit = (const float*)d_in[23];
    const float* Wenc   = (const float*)d_in[24];
    const float* Wdec   = (const float*)d_in[25];

    cudaFuncSetAttribute(k_mega, cudaFuncAttributeMaxDynamicSharedMemorySize, 147456);

    // 3 launches total: setup, tiled GEMMs, megakernel
    k_setup<<<3457, 128>>>(ys, embed, hs, hlens);
    k_tiled_all<<<4400, 256>>>(W1_W, b1_W, W1_Wx, b1_Wx, hs, Wenc);

    MKArgs a;
    a.hs = hs; a.U1 = U1; a.Ux1 = Ux1; a.U2 = U2; a.b2 = b2; a.Wc = Wc;
    a.Ux2 = Ux2; a.bUx2 = bUx2; a.Wcx = Wcx; a.Ws = Ws; a.bs = bs;
    a.Wy = Wy; a.We = We; a.Wlogit = Wlogit; a.blogit = blogit;
    a.Wdec = Wdec; a.Winit = Winit; a.binit = binit; a.hlens = hlens;
    a.out = (float*)d_out;
    k_mega<<<NBLK, NTHR, 147456>>>(a);
}

// round 11
// speedup vs baseline: 1.4400x; 1.4400x over previous
#include <cuda_runtime.h>
#include <cstdint>
#include <math.h>

// B=32, T=500, E=1024, D=1024, EMB=256, O=5000, olen=100, A=512
#define NBLK 296
#define NTHR 256

// ---------------- scratch layout (floats) ----------------
#define OFF_EYS   ((size_t)0)          // (100,32,256)
#define OFF_SB    ((size_t)819200)     // (100,32,2048)
#define OFF_SBX   ((size_t)7372800)    // (100,32,1024)
#define OFF_ENC   ((size_t)10649600)   // (32,500,512)
#define OFF_HSUM  ((size_t)18841600)   // (32,1024)
#define OFF_H     ((size_t)18874368)
#define OFF_H1    ((size_t)18907136)
#define OFF_C     ((size_t)18939904)
#define OFF_YM    ((size_t)18972672)   // (100,32)
#define OFF_L512  ((size_t)18975872)   // (32,512)
#define OFF_MS    ((size_t)18992256)   // (32,8,2)
#define OFF_EXP   ((size_t)18992768)   // (32,5000)
#define OFF_PA    ((size_t)19152768)   // 12*131072 max
#define OFF_PB    ((size_t)20725632)   // 36*32768 max
#define SZ_TOTAL  ((size_t)21905280)

__device__ float g_scratch[SZ_TOTAL];
__device__ unsigned g_bar_cnt;
__device__ unsigned g_bar_cnt2;

// ---------------- grid barrier: REDG arrive + acquire poll ----------------
__device__ __forceinline__ void gsync(unsigned& gen) {
    gen += NBLK;
    __syncthreads();
    if (threadIdx.x == 0) {
        asm volatile("red.release.gpu.global.add.u32 [%0], 1;"
                     :: "l"(&g_bar_cnt) : "memory");
        unsigned v;
        while (true) {
            asm volatile("ld.acquire.gpu.global.u32 %0, [%1];"
                         : "=r"(v) : "l"(&g_bar_cnt) : "memory");
            if ((int)(v - gen) >= 0) break;
            __nanosleep(32);
        }
    }
    __syncthreads();
}

__device__ __forceinline__ float sigm(float x) { return 1.f / (1.f + expf(-x)); }

// ---------------- GEMM building blocks (32 rows x 128 cols tile) ----------------
// abuf: [32(kk)][32(row)]; wbuf: [32(kk)][128(col)]
__device__ __forceinline__ void load_A(const float* A, int ldA, int k0, float* sAT) {
    int tid = threadIdx.x;
    int r = tid & 31, q = tid >> 5;
    float4 v = *(const float4*)(A + (size_t)r * ldA + k0 + q * 4);
    sAT[(q*4+0)*32 + r] = v.x; sAT[(q*4+1)*32 + r] = v.y;
    sAT[(q*4+2)*32 + r] = v.z; sAT[(q*4+3)*32 + r] = v.w;
}

__device__ __forceinline__ void load_W_async(const float* W, int ldW, int k0,
                                             int colBase, int ncols, float* sWdst) {
    unsigned sbase = (unsigned)__cvta_generic_to_shared(sWdst);
    int tid = threadIdx.x;
    #pragma unroll
    for (int v4 = 0; v4 < 4; v4++) {
        int id = tid + v4 * 256;
        int kr = id >> 5;
        int c4 = (id & 31) << 2;
        int rem = ncols - c4;
        int sz = rem >= 4 ? 16 : (rem > 0 ? rem * 4 : 0);
        int cc = (sz > 0) ? c4 : 0;
        const float* src = W + (size_t)(k0 + kr) * ldW + colBase + cc;
        unsigned d = sbase + (unsigned)((kr * 128 + c4) * 4);
        asm volatile("cp.async.cg.shared.global [%0], [%1], 16, %2;"
                     :: "r"(d), "l"(src), "r"(sz));
    }
}

// packed f32x2 MMA: acc[i][j] holds rows (rt*4+2i, rt*4+2i+1), col ct*4+j
__device__ __forceinline__ void mma_chunk(unsigned long long acc[2][4],
                                          const float* sAT, const float* sW) {
    int tid = threadIdx.x;
    int ct = tid & 31, rt = tid >> 5;
    #pragma unroll
    for (int kk = 0; kk < 32; kk++) {
        const unsigned long long* ap =
            (const unsigned long long*)(sAT + kk * 32 + rt * 4);
        unsigned long long a0 = ap[0], a1 = ap[1];
        float4 w = *(const float4*)(sW + kk * 128 + ct * 4);
        unsigned long long w0, w1, w2, w3;
        asm("mov.b64 %0, {%1,%1};" : "=l"(w0) : "f"(w.x));
        asm("mov.b64 %0, {%1,%1};" : "=l"(w1) : "f"(w.y));
        asm("mov.b64 %0, {%1,%1};" : "=l"(w2) : "f"(w.z));
        asm("mov.b64 %0, {%1,%1};" : "=l"(w3) : "f"(w.w));
        #define F2X(ac, av, wv) \
            asm("fma.rn.f32x2 %0, %1, %2, %0;" : "+l"(ac) : "l"(av), "l"(wv));
        F2X(acc[0][0], a0, w0) F2X(acc[0][1], a0, w1)
        F2X(acc[0][2], a0, w2) F2X(acc[0][3], a0, w3)
        F2X(acc[1][0], a1, w0) F2X(acc[1][1], a1, w1)
        F2X(acc[1][2], a1, w2) F2X(acc[1][3], a1, w3)
        #undef F2X
    }
}

__device__ __forceinline__ void store_tile(unsigned long long acc[2][4],
                                           float* outBase, int Ntot, int ncols) {
    int tid = threadIdx.x;
    int ct = tid & 31, rt = tid >> 5;
    int c = ct * 4;
    #pragma unroll
    for (int i = 0; i < 2; i++) {
        float lo[4], hi[4];
        #pragma unroll
        for (int j = 0; j < 4; j++)
            asm("mov.b64 {%0,%1}, %2;" : "=f"(lo[j]), "=f"(hi[j]) : "l"(acc[i][j]));
        float* d0 = outBase + (size_t)(rt * 4 + 2 * i) * Ntot + c;
        float* d1 = outBase + (size_t)(rt * 4 + 2 * i + 1) * Ntot + c;
        if (c + 4 <= ncols) {
            *(float4*)d0 = make_float4(lo[0], lo[1], lo[2], lo[3]);
            *(float4*)d1 = make_float4(hi[0], hi[1], hi[2], hi[3]);
        } else {
            #pragma unroll
            for (int q = 0; q < 4; q++)
                if (c + q < ncols) { d0[q] = lo[q]; d1[q] = hi[q]; }
        }
    }
}

struct GPair { const float* A; int ldA; const float* W; int ldW; int K; };

// double-buffered pipelined tile: cp.async W(i+1) overlaps compute(i)
__device__ void gemm_tile(const GPair* pr, int np, int ks, int KS,
                          int colBase, int ncols, float* outSlot, int Ntot,
                          float* abuf, float* wbuf) {
    unsigned long long acc[2][4] = {};
    int pidx[8], koff[8];
    int m = 0, gc = 0;
    for (int p = 0; p < np; p++)
        for (int k0 = 0; k0 < pr[p].K; k0 += 32)
            if ((gc++ % KS) == ks) { pidx[m] = p; koff[m] = k0; m++; }

    __syncthreads();   // protect smem from previous tile's in-flight readers
    if (m > 0) {
        load_W_async(pr[pidx[0]].W, pr[pidx[0]].ldW, koff[0], colBase, ncols, wbuf);
        asm volatile("cp.async.commit_group;" ::: "memory");
        load_A(pr[pidx[0]].A, pr[pidx[0]].ldA, koff[0], abuf);
    }
    for (int i = 0; i < m; i++) {
        asm volatile("cp.async.wait_group 0;" ::: "memory");
        __syncthreads();
        if (i + 1 < m) {
            load_W_async(pr[pidx[i+1]].W, pr[pidx[i+1]].ldW, koff[i+1],
                         colBase, ncols, wbuf + ((i + 1) & 1) * 4096);
            asm volatile("cp.async.commit_group;" ::: "memory");
            load_A(pr[pidx[i+1]].A, pr[pidx[i+1]].ldA, koff[i+1],
                   abuf + ((i + 1) & 1) * 1024);
        }
        mma_chunk(acc, abuf + (i & 1) * 1024, wbuf + (i & 1) * 4096);
    }
    store_tile(acc, outSlot, Ntot, ncols);
}

// ---------------- 64x64 tiled SGEMM (precompute phase, per block) ----------
__device__ void tiled64(const float* __restrict__ A, const float* __restrict__ W,
                        const float* __restrict__ bias, float* __restrict__ C,
                        int N, int K, int act, int cx, int cy, float* USM) {
    float* sAT = USM;          // [16][68]
    float* sW  = USM + 1088;   // [16][64]
    int rowBase = cy << 6;
    int colBase = cx << 6;
    int tx = threadIdx.x & 15;
    int ty = threadIdx.x >> 4;
    float acc[4][4];
    #pragma unroll
    for (int i = 0; i < 4; i++)
        #pragma unroll
        for (int j = 0; j < 4; j++) acc[i][j] = 0.f;

    for (int k0 = 0; k0 < K; k0 += 16) {
        __syncthreads();
        {
            int r = threadIdx.x >> 2;
            int c4 = (threadIdx.x & 3) << 2;
            float4 v = *(const float4*)(A + (size_t)(rowBase + r) * K + k0 + c4);
            sAT[(c4+0)*68 + r] = v.x; sAT[(c4+1)*68 + r] = v.y;
            sAT[(c4+2)*68 + r] = v.z; sAT[(c4+3)*68 + r] = v.w;
            int kr = threadIdx.x >> 4;
            int wc = (threadIdx.x & 15) << 2;
            *(float4*)&sW[kr*64 + wc] = *(const float4*)(W + (size_t)(k0 + kr) * N + colBase + wc);
        }
        __syncthreads();
        #pragma unroll
        for (int kk = 0; kk < 16; kk++) {
            float4 a4 = *(const float4*)&sAT[kk*68 + (ty << 2)];
            float4 w4 = *(const float4*)&sW[kk*64 + (tx << 2)];
            float av[4] = {a4.x, a4.y, a4.z, a4.w};
            float wv[4] = {w4.x, w4.y, w4.z, w4.w};
            #pragma unroll
            for (int i = 0; i < 4; i++)
                #pragma unroll
                for (int j = 0; j < 4; j++)
                    acc[i][j] = fmaf(av[i], wv[j], acc[i][j]);
        }
    }
    #pragma unroll
    for (int i = 0; i < 4; i++) {
        int r = rowBase + (ty << 2) + i;
        #pragma unroll
        for (int j = 0; j < 4; j++) {
            int c = colBase + (tx << 2) + j;
            float v = acc[i][j];
            if (bias) v += bias[c];
            if (act == 1) v = tanhf(v);
            C[(size_t)r * N + c] = v;
        }
    }
}

// ---------------- megakernel ----------------
struct MKArgs {
    const float *hs, *embed, *W1_W, *b1_W, *W1_Wx, *b1_Wx, *Wenc;
    const float *U1, *Ux1, *U2, *b2, *Wc, *Ux2, *bUx2, *Wcx;
    const float *Ws, *bs, *Wy, *We, *Wlogit, *blogit, *Wdec, *Winit, *binit;
    const int *hlens, *ys;
    float* out;
};

__global__ void __launch_bounds__(NTHR, 2) k_mega(MKArgs a) {
    extern __shared__ float SM[];
    float* abuf = SM;          // 2048 floats (2 x 32x32)
    float* wbuf = SM + 2048;   // 8192 floats (2 x 32x128)

    float* eys  = g_scratch + OFF_EYS;
    float* sb   = g_scratch + OFF_SB;
    float* sbx  = g_scratch + OFF_SBX;
    float* enc  = g_scratch + OFF_ENC;
    float* hsum = g_scratch + OFF_HSUM;
    float* h    = g_scratch + OFF_H;
    float* h1   = g_scratch + OFF_H1;
    float* cvec = g_scratch + OFF_C;
    float* ym   = g_scratch + OFF_YM;
    float* l512 = g_scratch + OFF_L512;
    float* ms   = g_scratch + OFF_MS;
    float* expb = g_scratch + OFF_EXP;
    float* pA   = g_scratch + OFF_PA;
    float* pB   = g_scratch + OFF_PB;

    const int tid = threadIdx.x;
    unsigned gen = 0;

    // ===== phase 0a: setup (ymask, eys gather, hsum) =====
    if (blockIdx.x == 0 && tid < 32) {
        int b = tid;
        int yl = 0;
        for (int j = 0; j < 99; j++) yl += (a.ys[b * 99 + j] != -1) ? 1 : 0;
        for (int i = 0; i < 100; i++)
            ym[i * 32 + b] = (i < yl + 1) ? 1.f : 0.f;
    }
    for (int idx4 = blockIdx.x * NTHR + tid; idx4 < 204800; idx4 += NBLK * NTHR) {
        int row = idx4 >> 6;              // i*32 + b
        int i = row >> 5, b = row & 31;
        int tok = 4999;
        if (i > 0) { int v = a.ys[b * 99 + i - 1]; tok = (v < 0) ? 4999 : v; }
        int c4 = (idx4 & 63) << 2;
        *(float4*)&eys[(size_t)row * 256 + c4] =
            *(const float4*)&a.embed[(size_t)tok * 256 + c4];
    }
    for (int t = blockIdx.x; t < 256; t += NBLK) {   // hsum
        int b = t >> 3, ech = t & 7;
        if (tid < 128) {
            int e = ech * 128 + tid;
            const float* base = a.hs + (size_t)b * 512000 + e;
            float s0 = 0.f, s1 = 0.f;
            for (int tt = 0; tt < 500; tt += 2) {
                s0 += base[(size_t)tt * 1024];
                s1 += base[(size_t)(tt + 1) * 1024];
            }
            hsum[b * 1024 + e] = (s0 + s1) / (float)a.hlens[b];
        }
    }
    gsync(gen);

    // ===== phase 0b: sb, sbx, enc via 64x64 tiles (4400 tiles) =====
    for (int t = blockIdx.x; t < 4400; t += NBLK) {
        if (t < 1600)       tiled64(eys, a.W1_W, a.b1_W, sb, 2048, 256, 0,
                                    t % 32, t / 32, SM);
        else if (t < 2400)  tiled64(eys, a.W1_Wx, a.b1_Wx, sbx, 1024, 256, 0,
                                    (t - 1600) % 16, (t - 1600) / 16, SM);
        else                tiled64(a.hs, a.Wenc, nullptr, enc, 512, 1024, 1,
                                    (t - 2400) % 8, (t - 2400) / 8, SM);
    }
    gsync(gen);

    // ===== h0 = hsum @ Winit + binit : 128 tiles (8 ct x 16 ks) =====
    for (int t = blockIdx.x; t < 128; t += NBLK) {
        int ct = t & 7, ks = t >> 3;
        GPair p = {hsum, 1024, a.Winit, 1024, 1024};
        gemm_tile(&p, 1, ks, 16, ct * 128, 128,
                  pA + (size_t)ks * 32768 + ct * 128, 1024, abuf, wbuf);
    }
    gsync(gen);
    for (int idx = blockIdx.x * NTHR + tid; idx < 32768; idx += NBLK * NTHR) {
        float s = a.binit[idx & 1023];
        #pragma unroll 4
        for (int sI = 0; sI < 16; sI++) s += pA[(size_t)sI * 32768 + idx];
        h[idx] = s;
    }
    gsync(gen);

    for (int step = 0; step < 100; step++) {
        // ===== phase 1: fused 9b(step-1) + gate1 = [h@U1 | h@Ux1], 288 tiles =====
        if (step > 0) {
            for (int t = blockIdx.x; t < 256; t += NBLK) {
                int b = t & 31, q = t >> 5;
                float gm = -1e30f;
                #pragma unroll
                for (int w = 0; w < 8; w++) gm = fmaxf(gm, ms[(b * 8 + w) * 2]);
                float gs = 0.f;
                #pragma unroll
                for (int w = 0; w < 8; w++)
                    gs += ms[(b * 8 + w) * 2 + 1] * expf(ms[(b * 8 + w) * 2] - gm);
                float scale = expf(ms[(b * 8 + q) * 2] - gm) / gs;
                float* o = a.out + (size_t)b * 500000 + (size_t)(step - 1) * 5000 + q * 625;
                const float* src = expb + (size_t)b * 5000 + q * 625;
                for (int j0 = tid; j0 < 625; j0 += NTHR) o[j0] = src[j0] * scale;
            }
        }
        for (int t = blockIdx.x; t < 288; t += NBLK) {
            int ct = t % 24, ks = t / 24;      // KS=12
            if (ct < 16) {
                GPair p = {h, 1024, a.U1, 2048, 1024};
                gemm_tile(&p, 1, ks, 12, ct * 128, 128,
                          pA + (size_t)ks * 98304 + ct * 128, 3072, abuf, wbuf);
            } else {
                GPair p = {h, 1024, a.Ux1, 1024, 1024};
                gemm_tile(&p, 1, ks, 12, (ct - 16) * 128, 128,
                          pA + (size_t)ks * 98304 + 2048 + (ct - 16) * 128, 3072,
                          abuf, wbuf);
            }
        }
        gsync(gen);

        // ===== phase 2: ew1 elementwise (12-slot reduce) -> h1 =====
        for (int idx = blockIdx.x * NTHR + tid; idx < 32768; idx += NBLK * NTHR) {
            int r = idx >> 10, j = idx & 1023;
            float prv = 0.f, uv = 0.f, hx = 0.f;
            #pragma unroll
            for (int s = 0; s < 12; s++) {
                const float* P = pA + (size_t)s * 98304 + (size_t)r * 3072;
                prv += P[j]; uv += P[1024 + j]; hx += P[2048 + j];
            }
            const float* x_ = sb + (size_t)step * 65536 + (size_t)r * 2048;
            prv = sigm(prv + x_[j]);
            uv  = sigm(uv + x_[1024 + j]);
            float ht = tanhf(hx * prv + sbx[(size_t)step * 32768 + r * 1024 + j]);
            float hold = h[idx];
            float m = ym[step * 32 + r];
            h1[idx] = m * (uv * hold + (1.f - uv) * ht) + (1.f - m) * hold;
        }
        gsync(gen);

        // ===== phase 2b: dq partials = h1 @ Wdec, 64 tiles (4 ct x 16 ks) =====
        for (int t = blockIdx.x; t < 64; t += NBLK) {
            int ct = t & 3, ks = t >> 2;       // KS=16, 2 chunks
            GPair p = {h1, 1024, a.Wdec, 512, 1024};
            gemm_tile(&p, 1, ks, 16, ct * 128, 128,
                      pB + (size_t)ks * 16384 + ct * 128, 512, abuf, wbuf);
        }
        gsync(gen);

        // ===== phase 3: attention scores en -> (stored in smem per tile) =====
        // 288 tiles: (b, tchunk of 56); scores written directly where phase 4
        // will re-read them; we store to expb-area? No: keep en in scratch pA
        // region reuse: use pB tail?  Simplest: dedicated small array in pA
        // is free (pA reused next at phase5).  Use pA + 11*98304 area? Risky.
        // Use l512 area? too small.  Use cvec? needed later.  Use en region:
        {
        }
        for (int t = blockIdx.x; t < 288; t += NBLK) {
            int b = t & 31, tch = t >> 5;      // 9 chunks of 56
            __syncthreads();
            float* dqs = SM;                   // 512
            for (int j = tid; j < 512; j += NTHR) {
                float s = 0.f;
                #pragma unroll
                for (int sI = 0; sI < 16; sI++)
                    s += pB[(size_t)sI * 16384 + b * 512 + j];
                dqs[j] = tanhf(s);
            }
            __syncthreads();
            int w = tid >> 5, l = tid & 31;
            int hl = a.hlens[b];
            int tstop = tch * 56 + 56; if (tstop > 500) tstop = 500;
            for (int tt = tch * 56 + w; tt < tstop; tt += 8) {
                const float* row = enc + ((size_t)b * 500 + tt) * 512;
                float s = 0.f;
                #pragma unroll
                for (int q = 0; q < 16; q++)
                    s = fmaf(row[l + q * 32], dqs[l + q * 32], s);
                #pragma unroll
                for (int o = 16; o; o >>= 1) s += __shfl_xor_sync(0xffffffffu, s, o);
                // en stored into expb area (reused scratch, safe this phase)
                if (l == 0) expb[b * 500 + tt] = (tt < hl) ? s : -1e9f;
            }
            __syncthreads();
        }
        gsync(gen);

        // ===== phase 4: softmax(en) + context c, 256 tiles (b x 8 e-chunks) =====
        for (int t = blockIdx.x; t < 256; t += NBLK) {
            int b = t & 31, ech = t >> 5;
            float* ws  = SM;                   // 500
            float* red = SM + 512;             // 8
            float* cp  = SM + 528;             // 256
            __syncthreads();
            const float* enb = expb + b * 500;
            float v0 = (tid < 500) ? enb[tid] : -1e30f;
            float v1 = (tid + 256 < 500) ? enb[tid + 256] : -1e30f;
            float lm = fmaxf(v0, v1);
            #pragma unroll
            for (int o = 16; o; o >>= 1) lm = fmaxf(lm, __shfl_xor_sync(0xffffffffu, lm, o));
            if ((tid & 31) == 0) red[tid >> 5] = lm;
            __syncthreads();
            float gm = red[0];
            #pragma unroll
            for (int w = 1; w < 8; w++) gm = fmaxf(gm, red[w]);
            float e0 = (tid < 500) ? expf(v0 - gm) : 0.f;
            float e1 = (tid + 256 < 500) ? expf(v1 - gm) : 0.f;
            if (tid < 500) ws[tid] = e0;
            if (tid + 256 < 500) ws[tid + 256] = e1;
            float ls = e0 + e1;
            #pragma unroll
            for (int o = 16; o; o >>= 1) ls += __shfl_xor_sync(0xffffffffu, ls, o);
            __syncthreads();
            if ((tid & 31) == 0) red[tid >> 5] = ls;
            __syncthreads();
            float tot = 0.f;
            #pragma unroll
            for (int w = 0; w < 8; w++) tot += red[w];
            float inv = 1.f / tot;
            int e = ech * 128 + (tid & 127);
            int th = tid >> 7;
            const float* base = a.hs + (size_t)b * 512000 + e + (size_t)th * 250 * 1024;
            const float* wsb = ws + th * 250;
            float s0 = 0.f, s1 = 0.f;
            for (int t4 = 0; t4 < 250; t4 += 2) {
                s0 = fmaf(wsb[t4],     base[(size_t)t4 * 1024], s0);
                s1 = fmaf(wsb[t4 + 1], base[(size_t)(t4 + 1) * 1024], s1);
            }
            cp[tid] = s0 + s1;
            __syncthreads();
            if (tid < 128)
                cvec[b * 1024 + e] = (cp[tid] + cp[tid + 128]) * inv;
            __syncthreads();
        }
        gsync(gen);

        // ===== phase 5: gate2 = [h1@U2+c@Wc | h1@Ux2 | c@Wcx], 288 tiles =====
        for (int t = blockIdx.x; t < 288; t += NBLK) {
            if (t < 192) {
                int ct = t % 16, ks = t / 16;     // KS=12, 64 chunks (2 pairs)
                GPair p2[2] = {{h1, 1024, a.U2, 2048, 1024},
                               {cvec, 1024, a.Wc, 2048, 1024}};
                gemm_tile(p2, 2, ks, 12, ct * 128, 128,
                          pA + (size_t)ks * 131072 + ct * 128, 4096, abuf, wbuf);
            } else if (t < 240) {
                int tt = t - 192, ct = tt & 7, ks = tt >> 3;  // KS=6
                GPair p = {h1, 1024, a.Ux2, 1024, 1024};
                gemm_tile(&p, 1, ks, 6, ct * 128, 128,
                          pA + (size_t)ks * 131072 + 2048 + ct * 128, 4096, abuf, wbuf);
            } else {
                int tt = t - 240, ct = tt & 7, ks = tt >> 3;  // KS=6
                GPair p = {cvec, 1024, a.Wcx, 1024, 1024};
                gemm_tile(&p, 1, ks, 6, ct * 128, 128,
                          pA + (size_t)ks * 131072 + 3072 + ct * 128, 4096, abuf, wbuf);
            }
        }
        gsync(gen);

        // ===== phase 6a: ew2 elementwise -> h (=h2) =====
        for (int idx = blockIdx.x * NTHR + tid; idx < 32768; idx += NBLK * NTHR) {
            int r = idx >> 10, j = idx & 1023;
            float prv = 0.f, uv = 0.f, hx = 0.f, cx = 0.f;
            #pragma unroll
            for (int s = 0; s < 12; s++) {
                const float* P = pA + (size_t)s * 131072 + (size_t)r * 4096;
                prv += P[j]; uv += P[1024 + j];
            }
            #pragma unroll
            for (int s = 0; s < 6; s++) {
                const float* P = pA + (size_t)s * 131072 + (size_t)r * 4096;
                hx += P[2048 + j]; cx += P[3072 + j];
            }
            prv = sigm(prv + a.b2[j]);
            uv  = sigm(uv + a.b2[1024 + j]);
            float ht = tanhf((hx + a.bUx2[j]) * prv + cx);
            float h1v = h1[idx];
            float m = ym[step * 32 + r];
            h[idx] = m * (uv * h1v + (1.f - uv) * ht) + (1.f - m) * h1v;
        }
        gsync(gen);

        // ===== phase 6b: logit partials = h2@Ws + eys@Wy + c@We, 288 tiles =====
        for (int t = blockIdx.x; t < 288; t += NBLK) {
            int ct = t & 7, ks = t >> 3;        // KS=36, 72 chunks -> 2 each
            GPair p3[3] = {{h, 1024, a.Ws, 1024, 1024},
                           {eys + (size_t)step * 8192, 256, a.Wy, 1024, 256},
                           {cvec, 1024, a.We, 1024, 1024}};
            gemm_tile(p3, 3, ks, 36, ct * 128, 128,
                      pB + (size_t)ks * 32768 + ct * 128, 1024, abuf, wbuf);
        }
        gsync(gen);

        // ===== phase 7: pool (sum 36 slots + bias, pairwise max) -> l512 =====
        for (int idx = blockIdx.x * NTHR + tid; idx < 16384; idx += NBLK * NTHR) {
            int r = idx >> 9, p2 = idx & 511;
            float v0 = a.bs[2 * p2], v1 = a.bs[2 * p2 + 1];
            #pragma unroll 4
            for (int s = 0; s < 36; s++) {
                const float* P = pB + (size_t)s * 32768 + (size_t)r * 1024;
                v0 += P[2 * p2]; v1 += P[2 * p2 + 1];
            }
            l512[idx] = fmaxf(v0, v1);
        }
        gsync(gen);

        // ===== phase 8: logits5000 = l512 @ Wlogit, 280 tiles (40 ct x 7 ks) =====
        for (int t = blockIdx.x; t < 280; t += NBLK) {
            int ct = t % 40, ks = t / 40;        // KS=7, 16 chunks -> 2-3 each
            int ncols = 5000 - ct * 128; if (ncols > 128) ncols = 128;
            GPair p = {l512, 512, a.Wlogit, 5000, 512};
            gemm_tile(&p, 1, ks, 7, ct * 128, ncols,
                      pA + (size_t)ks * 160000 + ct * 128, 5000, abuf, wbuf);
        }
        gsync(gen);

        // ===== phase 9a: reduce 7 partials + local max + exp, 256 tiles =====
        for (int t = blockIdx.x; t < 256; t += NBLK) {
            int b = t & 31, q = t >> 5;          // cols [q*625, q*625+625)
            float* buf = SM;                     // 625
            float* red = SM + 640;               // 8
            __syncthreads();
            float lm = -1e30f;
            for (int j0 = tid; j0 < 625; j0 += NTHR) {
                int j = q * 625 + j0;
                float v = a.blogit[j];
                #pragma unroll
                for (int s = 0; s < 7; s++)
                    v += pA[(size_t)s * 160000 + (size_t)b * 5000 + j];
                buf[j0] = v;
                lm = fmaxf(lm, v);
            }
            #pragma unroll
            for (int o = 16; o; o >>= 1) lm = fmaxf(lm, __shfl_xor_sync(0xffffffffu, lm, o));
            if ((tid & 31) == 0) red[tid >> 5] = lm;
            __syncthreads();
            float gml = red[0];
            #pragma unroll
            for (int w = 1; w < 8; w++) gml = fmaxf(gml, red[w]);
            float ls = 0.f;
            for (int j0 = tid; j0 < 625; j0 += NTHR) {
                float e = expf(buf[j0] - gml);
                expb[(size_t)b * 5000 + q * 625 + j0] = e;
                ls += e;
            }
            #pragma unroll
            for (int o = 16; o; o >>= 1) ls += __shfl_xor_sync(0xffffffffu, ls, o);
            __syncthreads();
            if ((tid & 31) == 0) red[tid >> 5] = ls;
            __syncthreads();
            if (tid == 0) {
                float tot = 0.f;
                #pragma unroll
                for (int w = 0; w < 8; w++) tot += red[w];
                ms[(b * 8 + q) * 2]     = gml;
                ms[(b * 8 + q) * 2 + 1] = tot;
            }
            __syncthreads();
        }
        gsync(gen);
    }

    // ===== final 9b for step 99 =====
    for (int t = blockIdx.x; t < 256; t += NBLK) {
        int b = t & 31, q = t >> 5;
        float gm = -1e30f;
        #pragma unroll
        for (int w = 0; w < 8; w++) gm = fmaxf(gm, ms[(b * 8 + w) * 2]);
        float gs = 0.f;
        #pragma unroll
        for (int w = 0; w < 8; w++)
            gs += ms[(b * 8 + w) * 2 + 1] * expf(ms[(b * 8 + w) * 2] - gm);
        float scale = expf(ms[(b * 8 + q) * 2] - gm) / gs;
        float* o = a.out + (size_t)b * 500000 + (size_t)99 * 5000 + q * 625;
        const float* src = expb + (size_t)b * 5000 + q * 625;
        for (int j0 = tid; j0 < 625; j0 += NTHR) o[j0] = src[j0] * scale;
    }

    // ===== safe barrier-counter reset (last block to arrive resets) =====
    __syncthreads();
    if (tid == 0) {
        unsigned r;
        asm volatile("atom.acq_rel.gpu.global.add.u32 %0, [%1], 1;"
                     : "=r"(r) : "l"(&g_bar_cnt2) : "memory");
        if (r == NBLK - 1) {
            g_bar_cnt = 0;
            g_bar_cnt2 = 0;
            __threadfence();
        }
    }
}

// ---------------- host launcher: single kernel ----------------
extern "C" void kernel_launch(void* const* d_in, const int* in_sizes, int n_in,
                              void* d_out, int out_size) {
    MKArgs a;
    a.hs     = (const float*)d_in[0];
    a.hlens  = (const int*)  d_in[1];
    a.ys     = (const int*)  d_in[2];
    a.embed  = (const float*)d_in[3];
    a.W1_W   = (const float*)d_in[4];
    a.b1_W   = (const float*)d_in[5];
    a.W1_Wx  = (const float*)d_in[6];
    a.b1_Wx  = (const float*)d_in[7];
    a.U1     = (const float*)d_in[8];
    a.Ux1    = (const float*)d_in[9];
    a.U2     = (const float*)d_in[10];
    a.b2     = (const float*)d_in[11];
    a.Wc     = (const float*)d_in[12];
    a.Ux2    = (const float*)d_in[13];
    a.bUx2   = (const float*)d_in[14];
    a.Wcx    = (const float*)d_in[15];
    a.Winit  = (const float*)d_in[16];
    a.binit  = (const float*)d_in[17];
    a.Ws     = (const float*)d_in[18];
    a.bs     = (const float*)d_in[19];
    a.Wy     = (const float*)d_in[20];
    a.We     = (const float*)d_in[21];
    a.Wlogit = (const float*)d_in[22];
    a.blogit = (const float*)d_in[23];
    a.Wenc   = (const float*)d_in[24];
    a.Wdec   = (const float*)d_in[25];
    a.out    = (float*)d_out;

    cudaFuncSetAttribute(k_mega, cudaFuncAttributeMaxDynamicSharedMemorySize, 40960);
    k_mega<<<NBLK, NTHR, 40960>>>(a);
}

// round 12
// speedup vs baseline: 1.4860x; 1.0319x over previous
#include <cuda_runtime.h>
#include <cstdint>
#include <math.h>

// B=32, T=500, E=1024, D=1024, EMB=256, O=5000, olen=100, A=512
#define NBLK 296
#define NTHR 256

// ---------------- scratch layout (floats) ----------------
#define OFF_EYS   ((size_t)0)          // (100,32,256)
#define OFF_SB    ((size_t)819200)     // (100,32,2048)
#define OFF_SBX   ((size_t)7372800)    // (100,32,1024)
#define OFF_ENC   ((size_t)10649600)   // (32,500,512)
#define OFF_YW    ((size_t)18841600)   // (100,32,1024) eys@Wy precomputed
#define OFF_HSUM  ((size_t)22118400)   // (32,1024)
#define OFF_H     ((size_t)22151168)
#define OFF_H1    ((size_t)22183936)
#define OFF_C     ((size_t)22216704)
#define OFF_YM    ((size_t)22249472)   // (100,32)
#define OFF_L512  ((size_t)22252672)   // (32,512)
#define OFF_MS    ((size_t)22269056)   // (32,8,2)
#define OFF_EXP   ((size_t)22269568)   // (32,5000)
#define OFF_CP    ((size_t)22429568)   // (32,9,1024) ctx partials
#define OFF_AST   ((size_t)22724480)   // (32,9,2) attn stats
#define OFF_PA    ((size_t)22725056)   // 1,179,648
#define OFF_PB    ((size_t)23904704)   // 1,179,648
#define SZ_TOTAL  ((size_t)25084352)

__device__ float g_scratch[SZ_TOTAL];
__device__ unsigned g_bar_cnt;
__device__ unsigned g_bar_cnt2;

// ---------------- grid barrier: REDG arrive + acquire poll ----------------
__device__ __forceinline__ void gsync(unsigned& gen) {
    gen += NBLK;
    __syncthreads();
    if (threadIdx.x == 0) {
        asm volatile("red.release.gpu.global.add.u32 [%0], 1;"
                     :: "l"(&g_bar_cnt) : "memory");
        unsigned v;
        while (true) {
            asm volatile("ld.acquire.gpu.global.u32 %0, [%1];"
                         : "=r"(v) : "l"(&g_bar_cnt) : "memory");
            if ((int)(v - gen) >= 0) break;
            __nanosleep(32);
        }
    }
    __syncthreads();
}

__device__ __forceinline__ float sigm(float x) { return 1.f / (1.f + expf(-x)); }

// ---------------- GEMM building blocks (32 rows x 128 cols tile) ----------------
__device__ __forceinline__ void load_A(const float* A, int ldA, int k0, float* sAT) {
    int tid = threadIdx.x;
    int r = tid & 31, q = tid >> 5;
    float4 v = *(const float4*)(A + (size_t)r * ldA + k0 + q * 4);
    sAT[(q*4+0)*32 + r] = v.x; sAT[(q*4+1)*32 + r] = v.y;
    sAT[(q*4+2)*32 + r] = v.z; sAT[(q*4+3)*32 + r] = v.w;
}

__device__ __forceinline__ void load_W_async(const float* W, int ldW, int k0,
                                             int colBase, int ncols, float* sWdst) {
    unsigned sbase = (unsigned)__cvta_generic_to_shared(sWdst);
    int tid = threadIdx.x;
    #pragma unroll
    for (int v4 = 0; v4 < 4; v4++) {
        int id = tid + v4 * 256;
        int kr = id >> 5;
        int c4 = (id & 31) << 2;
        int rem = ncols - c4;
        int sz = rem >= 4 ? 16 : (rem > 0 ? rem * 4 : 0);
        int cc = (sz > 0) ? c4 : 0;
        const float* src = W + (size_t)(k0 + kr) * ldW + colBase + cc;
        unsigned d = sbase + (unsigned)((kr * 128 + c4) * 4);
        asm volatile("cp.async.cg.shared.global [%0], [%1], 16, %2;"
                     :: "r"(d), "l"(src), "r"(sz));
    }
}

__device__ __forceinline__ void mma_chunk(unsigned long long acc[2][4],
                                          const float* sAT, const float* sW) {
    int tid = threadIdx.x;
    int ct = tid & 31, rt = tid >> 5;
    #pragma unroll
    for (int kk = 0; kk < 32; kk++) {
        const unsigned long long* ap =
            (const unsigned long long*)(sAT + kk * 32 + rt * 4);
        unsigned long long a0 = ap[0], a1 = ap[1];
        float4 w = *(const float4*)(sW + kk * 128 + ct * 4);
        unsigned long long w0, w1, w2, w3;
        asm("mov.b64 %0, {%1,%1};" : "=l"(w0) : "f"(w.x));
        asm("mov.b64 %0, {%1,%1};" : "=l"(w1) : "f"(w.y));
        asm("mov.b64 %0, {%1,%1};" : "=l"(w2) : "f"(w.z));
        asm("mov.b64 %0, {%1,%1};" : "=l"(w3) : "f"(w.w));
        #define F2X(ac, av, wv) \
            asm("fma.rn.f32x2 %0, %1, %2, %0;" : "+l"(ac) : "l"(av), "l"(wv));
        F2X(acc[0][0], a0, w0) F2X(acc[0][1], a0, w1)
        F2X(acc[0][2], a0, w2) F2X(acc[0][3], a0, w3)
        F2X(acc[1][0], a1, w0) F2X(acc[1][1], a1, w1)
        F2X(acc[1][2], a1, w2) F2X(acc[1][3], a1, w3)
        #undef F2X
    }
}

__device__ __forceinline__ void store_tile(unsigned long long acc[2][4],
                                           float* outBase, int Ntot, int ncols) {
    int tid = threadIdx.x;
    int ct = tid & 31, rt = tid >> 5;
    int c = ct * 4;
    #pragma unroll
    for (int i = 0; i < 2; i++) {
        float lo[4], hi[4];
        #pragma unroll
        for (int j = 0; j < 4; j++)
            asm("mov.b64 {%0,%1}, %2;" : "=f"(lo[j]), "=f"(hi[j]) : "l"(acc[i][j]));
        float* d0 = outBase + (size_t)(rt * 4 + 2 * i) * Ntot + c;
        float* d1 = outBase + (size_t)(rt * 4 + 2 * i + 1) * Ntot + c;
        if (c + 4 <= ncols) {
            *(float4*)d0 = make_float4(lo[0], lo[1], lo[2], lo[3]);
            *(float4*)d1 = make_float4(hi[0], hi[1], hi[2], hi[3]);
        } else {
            #pragma unroll
            for (int q = 0; q < 4; q++)
                if (c + q < ncols) { d0[q] = lo[q]; d1[q] = hi[q]; }
        }
    }
}

struct GPair { const float* A; int ldA; const float* W; int ldW; int K; };

__device__ void gemm_tile(const GPair* pr, int np, int ks, int KS,
                          int colBase, int ncols, float* outSlot, int Ntot,
                          float* abuf, float* wbuf) {
    unsigned long long acc[2][4] = {};
    int pidx[8], koff[8];
    int m = 0, gc = 0;
    for (int p = 0; p < np; p++)
        for (int k0 = 0; k0 < pr[p].K; k0 += 32)
            if ((gc++ % KS) == ks) { pidx[m] = p; koff[m] = k0; m++; }

    __syncthreads();
    if (m > 0) {
        load_W_async(pr[pidx[0]].W, pr[pidx[0]].ldW, koff[0], colBase, ncols, wbuf);
        asm volatile("cp.async.commit_group;" ::: "memory");
        load_A(pr[pidx[0]].A, pr[pidx[0]].ldA, koff[0], abuf);
    }
    for (int i = 0; i < m; i++) {
        asm volatile("cp.async.wait_group 0;" ::: "memory");
        __syncthreads();
        if (i + 1 < m) {
            load_W_async(pr[pidx[i+1]].W, pr[pidx[i+1]].ldW, koff[i+1],
                         colBase, ncols, wbuf + ((i + 1) & 1) * 4096);
            asm volatile("cp.async.commit_group;" ::: "memory");
            load_A(pr[pidx[i+1]].A, pr[pidx[i+1]].ldA, koff[i+1],
                   abuf + ((i + 1) & 1) * 1024);
        }
        mma_chunk(acc, abuf + (i & 1) * 1024, wbuf + (i & 1) * 4096);
    }
    store_tile(acc, outSlot, Ntot, ncols);
}

// ---------------- 64x64 tiled SGEMM (precompute) ----------
__device__ void tiled64(const float* __restrict__ A, const float* __restrict__ W,
                        const float* __restrict__ bias, float* __restrict__ C,
                        int N, int K, int act, int cx, int cy, float* USM) {
    float* sAT = USM;          // [16][68]
    float* sW  = USM + 1088;   // [16][64]
    int rowBase = cy << 6;
    int colBase = cx << 6;
    int tx = threadIdx.x & 15;
    int ty = threadIdx.x >> 4;
    float acc[4][4];
    #pragma unroll
    for (int i = 0; i < 4; i++)
        #pragma unroll
        for (int j = 0; j < 4; j++) acc[i][j] = 0.f;

    for (int k0 = 0; k0 < K; k0 += 16) {
        __syncthreads();
        {
            int r = threadIdx.x >> 2;
            int c4 = (threadIdx.x & 3) << 2;
            float4 v = *(const float4*)(A + (size_t)(rowBase + r) * K + k0 + c4);
            sAT[(c4+0)*68 + r] = v.x; sAT[(c4+1)*68 + r] = v.y;
            sAT[(c4+2)*68 + r] = v.z; sAT[(c4+3)*68 + r] = v.w;
            int kr = threadIdx.x >> 4;
            int wc = (threadIdx.x & 15) << 2;
            *(float4*)&sW[kr*64 + wc] = *(const float4*)(W + (size_t)(k0 + kr) * N + colBase + wc);
        }
        __syncthreads();
        #pragma unroll
        for (int kk = 0; kk < 16; kk++) {
            float4 a4 = *(const float4*)&sAT[kk*68 + (ty << 2)];
            float4 w4 = *(const float4*)&sW[kk*64 + (tx << 2)];
            float av[4] = {a4.x, a4.y, a4.z, a4.w};
            float wv[4] = {w4.x, w4.y, w4.z, w4.w};
            #pragma unroll
            for (int i = 0; i < 4; i++)
                #pragma unroll
                for (int j = 0; j < 4; j++)
                    acc[i][j] = fmaf(av[i], wv[j], acc[i][j]);
        }
    }
    #pragma unroll
    for (int i = 0; i < 4; i++) {
        int r = rowBase + (ty << 2) + i;
        #pragma unroll
        for (int j = 0; j < 4; j++) {
            int c = colBase + (tx << 2) + j;
            float v = acc[i][j];
            if (bias) v += bias[c];
            if (act == 1) v = tanhf(v);
            C[(size_t)r * N + c] = v;
        }
    }
}

// ---------------- megakernel ----------------
struct MKArgs {
    const float *hs, *embed, *W1_W, *b1_W, *W1_Wx, *b1_Wx, *Wenc;
    const float *U1, *Ux1, *U2, *b2, *Wc, *Ux2, *bUx2, *Wcx;
    const float *Ws, *bs, *Wy, *We, *Wlogit, *blogit, *Wdec, *Winit, *binit;
    const int *hlens, *ys;
    float* out;
};

__global__ void __launch_bounds__(NTHR, 2) k_mega(MKArgs a) {
    extern __shared__ float SM[];
    float* abuf = SM;          // 2048 floats
    float* wbuf = SM + 2048;   // 8192 floats

    float* eys  = g_scratch + OFF_EYS;
    float* sb   = g_scratch + OFF_SB;
    float* sbx  = g_scratch + OFF_SBX;
    float* enc  = g_scratch + OFF_ENC;
    float* yw   = g_scratch + OFF_YW;
    float* hsum = g_scratch + OFF_HSUM;
    float* h    = g_scratch + OFF_H;
    float* h1   = g_scratch + OFF_H1;
    float* cvec = g_scratch + OFF_C;
    float* ym   = g_scratch + OFF_YM;
    float* l512 = g_scratch + OFF_L512;
    float* ms   = g_scratch + OFF_MS;
    float* expb = g_scratch + OFF_EXP;
    float* cp   = g_scratch + OFF_CP;
    float* ast  = g_scratch + OFF_AST;
    float* pA   = g_scratch + OFF_PA;
    float* pB   = g_scratch + OFF_PB;

    const int tid = threadIdx.x;
    unsigned gen = 0;

    // ===== phase 0a: setup (ymask, eys gather, hsum) =====
    if (blockIdx.x == 0 && tid < 32) {
        int b = tid;
        int yl = 0;
        for (int j = 0; j < 99; j++) yl += (a.ys[b * 99 + j] != -1) ? 1 : 0;
        for (int i = 0; i < 100; i++)
            ym[i * 32 + b] = (i < yl + 1) ? 1.f : 0.f;
    }
    for (int idx4 = blockIdx.x * NTHR + tid; idx4 < 204800; idx4 += NBLK * NTHR) {
        int row = idx4 >> 6;
        int i = row >> 5, b = row & 31;
        int tok = 4999;
        if (i > 0) { int v = a.ys[b * 99 + i - 1]; tok = (v < 0) ? 4999 : v; }
        int c4 = (idx4 & 63) << 2;
        *(float4*)&eys[(size_t)row * 256 + c4] =
            *(const float4*)&a.embed[(size_t)tok * 256 + c4];
    }
    for (int t = blockIdx.x; t < 256; t += NBLK) {
        int b = t >> 3, ech = t & 7;
        if (tid < 128) {
            int e = ech * 128 + tid;
            const float* base = a.hs + (size_t)b * 512000 + e;
            float s0 = 0.f, s1 = 0.f;
            for (int tt = 0; tt < 500; tt += 2) {
                s0 += base[(size_t)tt * 1024];
                s1 += base[(size_t)(tt + 1) * 1024];
            }
            hsum[b * 1024 + e] = (s0 + s1) / (float)a.hlens[b];
        }
    }
    gsync(gen);

    // ===== phase 0b: sb, sbx, yW, enc via 64x64 tiles (5200 tiles) =====
    for (int t = blockIdx.x; t < 5200; t += NBLK) {
        if (t < 1600)       tiled64(eys, a.W1_W, a.b1_W, sb, 2048, 256, 0,
                                    t % 32, t / 32, SM);
        else if (t < 2400)  tiled64(eys, a.W1_Wx, a.b1_Wx, sbx, 1024, 256, 0,
                                    (t - 1600) % 16, (t - 1600) / 16, SM);
        else if (t < 3200)  tiled64(eys, a.Wy, nullptr, yw, 1024, 256, 0,
                                    (t - 2400) % 16, (t - 2400) / 16, SM);
        else                tiled64(a.hs, a.Wenc, nullptr, enc, 512, 1024, 1,
                                    (t - 3200) % 8, (t - 3200) / 8, SM);
    }
    gsync(gen);

    // ===== h0 = hsum @ Winit + binit : 128 tiles =====
    for (int t = blockIdx.x; t < 128; t += NBLK) {
        int ct = t & 7, ks = t >> 3;
        GPair p = {hsum, 1024, a.Winit, 1024, 1024};
        gemm_tile(&p, 1, ks, 16, ct * 128, 128,
                  pA + (size_t)ks * 32768 + ct * 128, 1024, abuf, wbuf);
    }
    gsync(gen);
    for (int idx = blockIdx.x * NTHR + tid; idx < 32768; idx += NBLK * NTHR) {
        float s = a.binit[idx & 1023];
        #pragma unroll 4
        for (int sI = 0; sI < 16; sI++) s += pA[(size_t)sI * 32768 + idx];
        h[idx] = s;
    }
    gsync(gen);

    for (int step = 0; step < 100; step++) {
        // ===== P1: fused 9b(step-1) + gate1 = [h@U1 | h@Ux1], 288 tiles =====
        if (step > 0) {
            for (int t = blockIdx.x; t < 256; t += NBLK) {
                int b = t & 31, q = t >> 5;
                float gm = -1e30f;
                #pragma unroll
                for (int w = 0; w < 8; w++) gm = fmaxf(gm, ms[(b * 8 + w) * 2]);
                float gs = 0.f;
                #pragma unroll
                for (int w = 0; w < 8; w++)
                    gs += ms[(b * 8 + w) * 2 + 1] * expf(ms[(b * 8 + w) * 2] - gm);
                float scale = expf(ms[(b * 8 + q) * 2] - gm) / gs;
                float* o = a.out + (size_t)b * 500000 + (size_t)(step - 1) * 5000 + q * 625;
                const float* src = expb + (size_t)b * 5000 + q * 625;
                for (int j0 = tid; j0 < 625; j0 += NTHR) o[j0] = src[j0] * scale;
            }
        }
        for (int t = blockIdx.x; t < 288; t += NBLK) {
            int ct = t % 24, ks = t / 24;      // KS=12
            if (ct < 16) {
                GPair p = {h, 1024, a.U1, 2048, 1024};
                gemm_tile(&p, 1, ks, 12, ct * 128, 128,
                          pA + (size_t)ks * 98304 + ct * 128, 3072, abuf, wbuf);
            } else {
                GPair p = {h, 1024, a.Ux1, 1024, 1024};
                gemm_tile(&p, 1, ks, 12, (ct - 16) * 128, 128,
                          pA + (size_t)ks * 98304 + 2048 + (ct - 16) * 128, 3072,
                          abuf, wbuf);
            }
        }
        gsync(gen);

        // ===== P2: ew1 (float4, 12-slot reduce) -> h1 =====
        for (int q = blockIdx.x * NTHR + tid; q < 8192; q += NBLK * NTHR) {
            int r = q >> 8, j4 = (q & 255) << 2;
            float4 pr = {0,0,0,0}, uv = {0,0,0,0}, hx = {0,0,0,0};
            #pragma unroll
            for (int s = 0; s < 12; s++) {
                const float* P = pA + (size_t)s * 98304 + (size_t)r * 3072;
                float4 v;
                v = *(const float4*)(P + j4);        pr.x+=v.x; pr.y+=v.y; pr.z+=v.z; pr.w+=v.w;
                v = *(const float4*)(P + 1024 + j4); uv.x+=v.x; uv.y+=v.y; uv.z+=v.z; uv.w+=v.w;
                v = *(const float4*)(P + 2048 + j4); hx.x+=v.x; hx.y+=v.y; hx.z+=v.z; hx.w+=v.w;
            }
            const float* x_ = sb + (size_t)step * 65536 + (size_t)r * 2048;
            float4 xa = *(const float4*)(x_ + j4);
            float4 xb = *(const float4*)(x_ + 1024 + j4);
            float4 xc = *(const float4*)(sbx + (size_t)step * 32768 + r * 1024 + j4);
            float4 ho = *(const float4*)(h + r * 1024 + j4);
            float m = ym[step * 32 + r];
            float4 res;
            #define EW1(L) { \
                float p_ = sigm(pr.L + xa.L); \
                float u_ = sigm(uv.L + xb.L); \
                float t_ = tanhf(hx.L * p_ + xc.L); \
                res.L = m * (u_ * ho.L + (1.f - u_) * t_) + (1.f - m) * ho.L; }
            EW1(x) EW1(y) EW1(z) EW1(w)
            #undef EW1
            *(float4*)(h1 + r * 1024 + j4) = res;
        }
        gsync(gen);

        // ===== P3: dq + h1@U2 + h1@Ux2 partials, 280 tiles (KS=10) =====
        for (int t = blockIdx.x; t < 280; t += NBLK) {
            if (t < 40) {
                int ct = t & 3, ks = t >> 2;
                GPair p = {h1, 1024, a.Wdec, 512, 1024};
                gemm_tile(&p, 1, ks, 10, ct * 128, 128,
                          pB + (size_t)ks * 16384 + ct * 128, 512, abuf, wbuf);
            } else if (t < 200) {
                int tt = t - 40, ct = tt % 16, ks = tt / 16;
                GPair p = {h1, 1024, a.U2, 2048, 1024};
                gemm_tile(&p, 1, ks, 10, ct * 128, 128,
                          pA + (size_t)ks * 98304 + ct * 128, 3072, abuf, wbuf);
            } else {
                int tt = t - 200, ct = tt & 7, ks = tt >> 3;
                GPair p = {h1, 1024, a.Ux2, 1024, 1024};
                gemm_tile(&p, 1, ks, 10, ct * 128, 128,
                          pA + (size_t)ks * 98304 + 2048 + ct * 128, 3072, abuf, wbuf);
            }
        }
        gsync(gen);

        // ===== P4: online-softmax attention, 288 tiles (b x 9 t-chunks of 56) =====
        for (int t = blockIdx.x; t < 288; t += NBLK) {
            int b = t & 31, tch = t >> 5;
            __syncthreads();
            float* dqs = SM;           // 512
            float* sc  = SM + 512;     // 56
            float* red = SM + 576;     // small
            for (int j = tid; j < 512; j += NTHR) {
                float s = 0.f;
                #pragma unroll
                for (int sI = 0; sI < 10; sI++)
                    s += pB[(size_t)sI * 16384 + b * 512 + j];
                dqs[j] = tanhf(s);
            }
            __syncthreads();
            int t0 = tch * 56;
            int tn = 500 - t0; if (tn > 56) tn = 56;
            int w = tid >> 5, l = tid & 31;
            int hl = a.hlens[b];
            for (int tt = w; tt < tn; tt += 8) {
                const float* row = enc + ((size_t)b * 500 + t0 + tt) * 512;
                float s = 0.f;
                #pragma unroll
                for (int qq = 0; qq < 16; qq++)
                    s = fmaf(row[l + qq * 32], dqs[l + qq * 32], s);
                #pragma unroll
                for (int o = 16; o; o >>= 1) s += __shfl_xor_sync(0xffffffffu, s, o);
                if (l == 0) sc[tt] = (t0 + tt < hl) ? s : -1e9f;
            }
            __syncthreads();
            if (tid < 32) {
                float mloc = -1e30f;
                for (int i = l; i < tn; i += 32) mloc = fmaxf(mloc, sc[i]);
                #pragma unroll
                for (int o = 16; o; o >>= 1) mloc = fmaxf(mloc, __shfl_xor_sync(0xffffffffu, mloc, o));
                float ssum = 0.f;
                for (int i = l; i < tn; i += 32) {
                    float e = expf(sc[i] - mloc);
                    sc[i] = e;
                    ssum += e;
                }
                #pragma unroll
                for (int o = 16; o; o >>= 1) ssum += __shfl_xor_sync(0xffffffffu, ssum, o);
                if (l == 0) {
                    ast[(b * 9 + tch) * 2]     = mloc;
                    ast[(b * 9 + tch) * 2 + 1] = ssum;
                }
            }
            __syncthreads();
            // ctx partial: 256 threads x 4 e-cols
            int e0 = tid * 4;
            float4 acc = {0,0,0,0};
            const float* hb = a.hs + (size_t)b * 512000 + (size_t)t0 * 1024 + e0;
            for (int tt = 0; tt < tn; tt++) {
                float wg = sc[tt];
                float4 hv = *(const float4*)(hb + (size_t)tt * 1024);
                acc.x = fmaf(wg, hv.x, acc.x);
                acc.y = fmaf(wg, hv.y, acc.y);
                acc.z = fmaf(wg, hv.z, acc.z);
                acc.w = fmaf(wg, hv.w, acc.w);
            }
            *(float4*)(cp + (size_t)(b * 9 + tch) * 1024 + e0) = acc;
            __syncthreads();
        }
        gsync(gen);

        // ===== P5: ctx combine -> cvec, 128 tiles (b x 4 e-chunks of 256) =====
        for (int t = blockIdx.x; t < 128; t += NBLK) {
            int b = t & 31, ech = t >> 5;
            float M = -1e30f;
            #pragma unroll
            for (int ch = 0; ch < 9; ch++) M = fmaxf(M, ast[(b * 9 + ch) * 2]);
            float Z = 0.f;
            float scl[9];
            #pragma unroll
            for (int ch = 0; ch < 9; ch++) {
                scl[ch] = expf(ast[(b * 9 + ch) * 2] - M);
                Z += ast[(b * 9 + ch) * 2 + 1] * scl[ch];
            }
            float inv = 1.f / Z;
            int e = ech * 256 + tid;
            float s = 0.f;
            #pragma unroll
            for (int ch = 0; ch < 9; ch++)
                s = fmaf(cp[(size_t)(b * 9 + ch) * 1024 + e], scl[ch], s);
            cvec[b * 1024 + e] = s * inv;
        }
        gsync(gen);

        // ===== P6: c@Wc | c@Wcx | c@We, 288 tiles (KS=9) =====
        for (int t = blockIdx.x; t < 288; t += NBLK) {
            if (t < 144) {
                int ct = t % 16, ks = t / 16;
                GPair p = {cvec, 1024, a.Wc, 2048, 1024};
                gemm_tile(&p, 1, ks, 9, ct * 128, 128,
                          pB + (size_t)ks * 131072 + ct * 128, 4096, abuf, wbuf);
            } else if (t < 216) {
                int tt = t - 144, ct = tt & 7, ks = tt >> 3;
                GPair p = {cvec, 1024, a.Wcx, 1024, 1024};
                gemm_tile(&p, 1, ks, 9, ct * 128, 128,
                          pB + (size_t)ks * 131072 + 2048 + ct * 128, 4096, abuf, wbuf);
            } else {
                int tt = t - 216, ct = tt & 7, ks = tt >> 3;
                GPair p = {cvec, 1024, a.We, 1024, 1024};
                gemm_tile(&p, 1, ks, 9, ct * 128, 128,
                          pB + (size_t)ks * 131072 + 3072 + ct * 128, 4096, abuf, wbuf);
            }
        }
        gsync(gen);

        // ===== P7: ew2 (float4) -> h (=h2) =====
        for (int q = blockIdx.x * NTHR + tid; q < 8192; q += NBLK * NTHR) {
            int r = q >> 8, j4 = (q & 255) << 2;
            float4 pr = {0,0,0,0}, uv = {0,0,0,0}, hx = {0,0,0,0}, cx = {0,0,0,0};
            #pragma unroll
            for (int s = 0; s < 10; s++) {
                const float* P = pA + (size_t)s * 98304 + (size_t)r * 3072;
                float4 v;
                v = *(const float4*)(P + j4);        pr.x+=v.x; pr.y+=v.y; pr.z+=v.z; pr.w+=v.w;
                v = *(const float4*)(P + 1024 + j4); uv.x+=v.x; uv.y+=v.y; uv.z+=v.z; uv.w+=v.w;
                v = *(const float4*)(P + 2048 + j4); hx.x+=v.x; hx.y+=v.y; hx.z+=v.z; hx.w+=v.w;
            }
            #pragma unroll
            for (int s = 0; s < 9; s++) {
                const float* P = pB + (size_t)s * 131072 + (size_t)r * 4096;
                float4 v;
                v = *(const float4*)(P + j4);        pr.x+=v.x; pr.y+=v.y; pr.z+=v.z; pr.w+=v.w;
                v = *(const float4*)(P + 1024 + j4); uv.x+=v.x; uv.y+=v.y; uv.z+=v.z; uv.w+=v.w;
                v = *(const float4*)(P + 2048 + j4); cx.x+=v.x; cx.y+=v.y; cx.z+=v.z; cx.w+=v.w;
            }
            float4 ba = *(const float4*)(a.b2 + j4);
            float4 bb = *(const float4*)(a.b2 + 1024 + j4);
            float4 bu = *(const float4*)(a.bUx2 + j4);
            float4 h1v = *(const float4*)(h1 + r * 1024 + j4);
            float m = ym[step * 32 + r];
            float4 res;
            #define EW2(L) { \
                float p_ = sigm(pr.L + ba.L); \
                float u_ = sigm(uv.L + bb.L); \
                float t_ = tanhf((hx.L + bu.L) * p_ + cx.L); \
                res.L = m * (u_ * h1v.L + (1.f - u_) * t_) + (1.f - m) * h1v.L; }
            EW2(x) EW2(y) EW2(z) EW2(w)
            #undef EW2
            *(float4*)(h + r * 1024 + j4) = res;
        }
        gsync(gen);

        // ===== P8: h2@Ws, 256 tiles (KS=32, m=1) =====
        for (int t = blockIdx.x; t < 256; t += NBLK) {
            int ct = t & 7, ks = t >> 3;
            GPair p = {h, 1024, a.Ws, 1024, 1024};
            gemm_tile(&p, 1, ks, 32, ct * 128, 128,
                      pA + (size_t)ks * 32768 + ct * 128, 1024, abuf, wbuf);
        }
        gsync(gen);

        // ===== P9: pool (32 Ws slots + 9 We slots + yW + bs, pairmax) -> l512 =====
        for (int idx = blockIdx.x * NTHR + tid; idx < 16384; idx += NBLK * NTHR) {
            int r = idx >> 9, p2 = idx & 511;
            float2 v = *(const float2*)(a.bs + 2 * p2);
            float2 yv = *(const float2*)(yw + (size_t)step * 32768 + r * 1024 + 2 * p2);
            v.x += yv.x; v.y += yv.y;
            #pragma unroll 8
            for (int s = 0; s < 32; s++) {
                float2 pv = *(const float2*)(pA + (size_t)s * 32768 + (size_t)r * 1024 + 2 * p2);
                v.x += pv.x; v.y += pv.y;
            }
            #pragma unroll
            for (int s = 0; s < 9; s++) {
                float2 pv = *(const float2*)(pB + (size_t)s * 131072 + (size_t)r * 4096 + 3072 + 2 * p2);
                v.x += pv.x; v.y += pv.y;
            }
            l512[idx] = fmaxf(v.x, v.y);
        }
        gsync(gen);

        // ===== P10: logits5000 = l512 @ Wlogit, 280 tiles (KS=7) =====
        for (int t = blockIdx.x; t < 280; t += NBLK) {
            int ct = t % 40, ks = t / 40;
            int ncols = 5000 - ct * 128; if (ncols > 128) ncols = 128;
            GPair p = {l512, 512, a.Wlogit, 5000, 512};
            gemm_tile(&p, 1, ks, 7, ct * 128, ncols,
                      pA + (size_t)ks * 160000 + ct * 128, 5000, abuf, wbuf);
        }
        gsync(gen);

        // ===== P11: reduce 7 partials + local max + exp, 256 tiles =====
        for (int t = blockIdx.x; t < 256; t += NBLK) {
            int b = t & 31, q = t >> 5;
            float* buf = SM;
            float* red = SM + 640;
            __syncthreads();
            float lm = -1e30f;
            for (int j0 = tid; j0 < 625; j0 += NTHR) {
                int j = q * 625 + j0;
                float v = a.blogit[j];
                #pragma unroll
                for (int s = 0; s < 7; s++)
                    v += pA[(size_t)s * 160000 + (size_t)b * 5000 + j];
                buf[j0] = v;
                lm = fmaxf(lm, v);
            }
            #pragma unroll
            for (int o = 16; o; o >>= 1) lm = fmaxf(lm, __shfl_xor_sync(0xffffffffu, lm, o));
            if ((tid & 31) == 0) red[tid >> 5] = lm;
            __syncthreads();
            float gml = red[0];
            #pragma unroll
            for (int w = 1; w < 8; w++) gml = fmaxf(gml, red[w]);
            float ls = 0.f;
            for (int j0 = tid; j0 < 625; j0 += NTHR) {
                float e = expf(buf[j0] - gml);
                expb[(size_t)b * 5000 + q * 625 + j0] = e;
                ls += e;
            }
            #pragma unroll
            for (int o = 16; o; o >>= 1) ls += __shfl_xor_sync(0xffffffffu, ls, o);
            __syncthreads();
            if ((tid & 31) == 0) red[tid >> 5] = ls;
            __syncthreads();
            if (tid == 0) {
                float tot = 0.f;
                #pragma unroll
                for (int w = 0; w < 8; w++) tot += red[w];
                ms[(b * 8 + q) * 2]     = gml;
                ms[(b * 8 + q) * 2 + 1] = tot;
            }
            __syncthreads();
        }
        gsync(gen);
    }

    // ===== final 9b for step 99 =====
    for (int t = blockIdx.x; t < 256; t += NBLK) {
        int b = t & 31, q = t >> 5;
        float gm = -1e30f;
        #pragma unroll
        for (int w = 0; w < 8; w++) gm = fmaxf(gm, ms[(b * 8 + w) * 2]);
        float gs = 0.f;
        #pragma unroll
        for (int w = 0; w < 8; w++)
            gs += ms[(b * 8 + w) * 2 + 1] * expf(ms[(b * 8 + w) * 2] - gm);
        float scale = expf(ms[(b * 8 + q) * 2] - gm) / gs;
        float* o = a.out + (size_t)b * 500000 + (size_t)99 * 5000 + q * 625;
        const float* src = expb + (size_t)b * 5000 + q * 625;
        for (int j0 = tid; j0 < 625; j0 += NTHR) o[j0] = src[j0] * scale;
    }

    // ===== safe barrier-counter reset =====
    __syncthreads();
    if (tid == 0) {
        unsigned r;
        asm volatile("atom.acq_rel.gpu.global.add.u32 %0, [%1], 1;"
                     : "=r"(r) : "l"(&g_bar_cnt2) : "memory");
        if (r == NBLK - 1) {
            g_bar_cnt = 0;
            g_bar_cnt2 = 0;
            __threadfence();
        }
    }
}

// ---------------- host launcher: single kernel ----------------
extern "C" void kernel_launch(void* const* d_in, const int* in_sizes, int n_in,
                              void* d_out, int out_size) {
    MKArgs a;
    a.hs     = (const float*)d_in[0];
    a.hlens  = (const int*)  d_in[1];
    a.ys     = (const int*)  d_in[2];
    a.embed  = (const float*)d_in[3];
    a.W1_W   = (const float*)d_in[4];
    a.b1_W   = (const float*)d_in[5];
    a.W1_Wx  = (const float*)d_in[6];
    a.b1_Wx  = (const float*)d_in[7];
    a.U1     = (const float*)d_in[8];
    a.Ux1    = (const float*)d_in[9];
    a.U2     = (const float*)d_in[10];
    a.b2     = (const float*)d_in[11];
    a.Wc     = (const float*)d_in[12];
    a.Ux2    = (const float*)d_in[13];
    a.bUx2   = (const float*)d_in[14];
    a.Wcx    = (const float*)d_in[15];
    a.Winit  = (const float*)d_in[16];
    a.binit  = (const float*)d_in[17];
    a.Ws     = (const float*)d_in[18];
    a.bs     = (const float*)d_in[19];
    a.Wy     = (const float*)d_in[20];
    a.We     = (const float*)d_in[21];
    a.Wlogit = (const float*)d_in[22];
    a.blogit = (const float*)d_in[23];
    a.Wenc   = (const float*)d_in[24];
    a.Wdec   = (const float*)d_in[25];
    a.out    = (float*)d_out;

    cudaFuncSetAttribute(k_mega, cudaFuncAttributeMaxDynamicSharedMemorySize, 40960);
    k_mega<<<NBLK, NTHR, 40960>>>(a);
}

// round 13
// speedup vs baseline: 1.5384x; 1.0353x over previous
#include <cuda_runtime.h>
#include <cstdint>
#include <math.h>

// B=32, T=500, E=1024, D=1024, EMB=256, O=5000, olen=100, A=512
#define NBLK 296
#define NTHR 256

// ---------------- scratch layout (floats) ----------------
#define OFF_EYS   ((size_t)0)          // (100,32,256)
#define OFF_SB    ((size_t)819200)     // (100,32,2048)
#define OFF_SBX   ((size_t)7372800)    // (100,32,1024)
#define OFF_ENC   ((size_t)10649600)   // (32,500,512)
#define OFF_YW    ((size_t)18841600)   // (100,32,1024) eys@Wy precomputed
#define OFF_HSUM  ((size_t)22118400)   // (32,1024)
#define OFF_H     ((size_t)22151168)
#define OFF_H1    ((size_t)22183936)
#define OFF_C     ((size_t)22216704)
#define OFF_YM    ((size_t)22249472)   // (100,32)
#define OFF_L512  ((size_t)22252672)   // (32,512)
#define OFF_MS    ((size_t)22269056)   // (32,8,2)
#define OFF_EXP   ((size_t)22269568)   // (32,5000)
#define OFF_CP    ((size_t)22429568)   // (32,9,1024) ctx partials
#define OFF_AST   ((size_t)22724480)   // (32,9,2) attn stats
#define OFF_PA    ((size_t)22725056)   // 1,179,648
#define OFF_PB    ((size_t)23904704)   // 1,179,648
#define SZ_TOTAL  ((size_t)25084352)

__device__ float g_scratch[SZ_TOTAL];
__device__ unsigned g_bar_cnt;
__device__ unsigned g_bar_cnt2;

// ---------------- grid barrier: REDG arrive + acquire poll ----------------
__device__ __forceinline__ void gsync(unsigned& gen) {
    gen += NBLK;
    __syncthreads();
    if (threadIdx.x == 0) {
        asm volatile("red.release.gpu.global.add.u32 [%0], 1;"
                     :: "l"(&g_bar_cnt) : "memory");
        unsigned v;
        while (true) {
            asm volatile("ld.acquire.gpu.global.u32 %0, [%1];"
                         : "=r"(v) : "l"(&g_bar_cnt) : "memory");
            if ((int)(v - gen) >= 0) break;
        }
    }
    __syncthreads();
}

__device__ __forceinline__ float sigm(float x) { return 1.f / (1.f + expf(-x)); }

// ---------------- GEMM building blocks (32 rows x 128 cols tile) ----------------
__device__ __forceinline__ void load_A(const float* A, int ldA, int k0, float* sAT) {
    int tid = threadIdx.x;
    int r = tid & 31, q = tid >> 5;
    float4 v = *(const float4*)(A + (size_t)r * ldA + k0 + q * 4);
    sAT[(q*4+0)*32 + r] = v.x; sAT[(q*4+1)*32 + r] = v.y;
    sAT[(q*4+2)*32 + r] = v.z; sAT[(q*4+3)*32 + r] = v.w;
}

__device__ __forceinline__ void load_W_async(const float* W, int ldW, int k0,
                                             int colBase, int ncols, float* sWdst) {
    unsigned sbase = (unsigned)__cvta_generic_to_shared(sWdst);
    int tid = threadIdx.x;
    #pragma unroll
    for (int v4 = 0; v4 < 4; v4++) {
        int id = tid + v4 * 256;
        int kr = id >> 5;
        int c4 = (id & 31) << 2;
        int rem = ncols - c4;
        int sz = rem >= 4 ? 16 : (rem > 0 ? rem * 4 : 0);
        int cc = (sz > 0) ? c4 : 0;
        const float* src = W + (size_t)(k0 + kr) * ldW + colBase + cc;
        unsigned d = sbase + (unsigned)((kr * 128 + c4) * 4);
        asm volatile("cp.async.cg.shared.global [%0], [%1], 16, %2;"
                     :: "r"(d), "l"(src), "r"(sz));
    }
}

// prefetch first W tile of an upcoming GEMM phase (issued during prior phase)
__device__ __forceinline__ void prefetchW(const float* W, int ldW, int k0,
                                          int colBase, int ncols, float* wbuf) {
    __syncthreads();   // ensure prior GEMM phase readers of wbuf are done
    load_W_async(W, ldW, k0, colBase, ncols, wbuf);
    asm volatile("cp.async.commit_group;" ::: "memory");
}

// packed f32x2 MMA, 8 rows x 2 cols per thread:
// acc[i][j] holds rows (rt*8+2i, rt*8+2i+1), col ct*2+j  (ct=tid&63, rt=tid>>6)
__device__ __forceinline__ void mma_chunk(unsigned long long acc[4][2],
                                          const float* sAT, const float* sW) {
    int tid = threadIdx.x;
    int ct = tid & 63, rt = tid >> 6;
    #pragma unroll
    for (int kk = 0; kk < 32; kk++) {
        const unsigned long long* ap =
            (const unsigned long long*)(sAT + kk * 32 + rt * 8);
        unsigned long long a0 = ap[0], a1 = ap[1], a2 = ap[2], a3 = ap[3];
        float2 w = *(const float2*)(sW + kk * 128 + ct * 2);
        unsigned long long w0, w1;
        asm("mov.b64 %0, {%1,%1};" : "=l"(w0) : "f"(w.x));
        asm("mov.b64 %0, {%1,%1};" : "=l"(w1) : "f"(w.y));
        #define F2X(ac, av, wv) \
            asm("fma.rn.f32x2 %0, %1, %2, %0;" : "+l"(ac) : "l"(av), "l"(wv));
        F2X(acc[0][0], a0, w0) F2X(acc[0][1], a0, w1)
        F2X(acc[1][0], a1, w0) F2X(acc[1][1], a1, w1)
        F2X(acc[2][0], a2, w0) F2X(acc[2][1], a2, w1)
        F2X(acc[3][0], a3, w0) F2X(acc[3][1], a3, w1)
        #undef F2X
    }
}

__device__ __forceinline__ void store_tile(unsigned long long acc[4][2],
                                           float* outBase, int Ntot, int ncols) {
    int tid = threadIdx.x;
    int ct = tid & 63, rt = tid >> 6;
    int c = ct * 2;
    if (c + 2 > ncols) return;   // ncols always even in this kernel
    #pragma unroll
    for (int i = 0; i < 4; i++) {
        float lo0, hi0, lo1, hi1;
        asm("mov.b64 {%0,%1}, %2;" : "=f"(lo0), "=f"(hi0) : "l"(acc[i][0]));
        asm("mov.b64 {%0,%1}, %2;" : "=f"(lo1), "=f"(hi1) : "l"(acc[i][1]));
        float* d0 = outBase + (size_t)(rt * 8 + 2 * i) * Ntot + c;
        float* d1 = outBase + (size_t)(rt * 8 + 2 * i + 1) * Ntot + c;
        *(float2*)d0 = make_float2(lo0, lo1);
        *(float2*)d1 = make_float2(hi0, hi1);
    }
}

struct GPair { const float* A; int ldA; const float* W; int ldW; int K; };

__device__ void gemm_tile(const GPair* pr, int np, int ks, int KS,
                          int colBase, int ncols, float* outSlot, int Ntot,
                          float* abuf, float* wbuf, int wpre) {
    unsigned long long acc[4][2] = {};
    int pidx[8], koff[8];
    int m = 0, gc = 0;
    for (int p = 0; p < np; p++)
        for (int k0 = 0; k0 < pr[p].K; k0 += 32)
            if ((gc++ % KS) == ks) { pidx[m] = p; koff[m] = k0; m++; }

    __syncthreads();
    if (m > 0) {
        if (!wpre) {
            load_W_async(pr[pidx[0]].W, pr[pidx[0]].ldW, koff[0], colBase, ncols, wbuf);
            asm volatile("cp.async.commit_group;" ::: "memory");
        }
        load_A(pr[pidx[0]].A, pr[pidx[0]].ldA, koff[0], abuf);
    }
    for (int i = 0; i < m; i++) {
        asm volatile("cp.async.wait_group 0;" ::: "memory");
        __syncthreads();
        if (i + 1 < m) {
            load_W_async(pr[pidx[i+1]].W, pr[pidx[i+1]].ldW, koff[i+1],
                         colBase, ncols, wbuf + ((i + 1) & 1) * 4096);
            asm volatile("cp.async.commit_group;" ::: "memory");
            load_A(pr[pidx[i+1]].A, pr[pidx[i+1]].ldA, koff[i+1],
                   abuf + ((i + 1) & 1) * 1024);
        }
        mma_chunk(acc, abuf + (i & 1) * 1024, wbuf + (i & 1) * 4096);
    }
    store_tile(acc, outSlot, Ntot, ncols);
}

// ---------------- 64x64 tiled SGEMM (precompute) ----------
__device__ void tiled64(const float* __restrict__ A, const float* __restrict__ W,
                        const float* __restrict__ bias, float* __restrict__ C,
                        int N, int K, int act, int cx, int cy, float* USM) {
    float* sAT = USM;          // [16][68]
    float* sW  = USM + 1088;   // [16][64]
    int rowBase = cy << 6;
    int colBase = cx << 6;
    int tx = threadIdx.x & 15;
    int ty = threadIdx.x >> 4;
    float acc[4][4];
    #pragma unroll
    for (int i = 0; i < 4; i++)
        #pragma unroll
        for (int j = 0; j < 4; j++) acc[i][j] = 0.f;

    for (int k0 = 0; k0 < K; k0 += 16) {
        __syncthreads();
        {
            int r = threadIdx.x >> 2;
            int c4 = (threadIdx.x & 3) << 2;
            float4 v = *(const float4*)(A + (size_t)(rowBase + r) * K + k0 + c4);
            sAT[(c4+0)*68 + r] = v.x; sAT[(c4+1)*68 + r] = v.y;
            sAT[(c4+2)*68 + r] = v.z; sAT[(c4+3)*68 + r] = v.w;
            int kr = threadIdx.x >> 4;
            int wc = (threadIdx.x & 15) << 2;
            *(float4*)&sW[kr*64 + wc] = *(const float4*)(W + (size_t)(k0 + kr) * N + colBase + wc);
        }
        __syncthreads();
        #pragma unroll
        for (int kk = 0; kk < 16; kk++) {
            float4 a4 = *(const float4*)&sAT[kk*68 + (ty << 2)];
            float4 w4 = *(const float4*)&sW[kk*64 + (tx << 2)];
            float av[4] = {a4.x, a4.y, a4.z, a4.w};
            float wv[4] = {w4.x, w4.y, w4.z, w4.w};
            #pragma unroll
            for (int i = 0; i < 4; i++)
                #pragma unroll
                for (int j = 0; j < 4; j++)
                    acc[i][j] = fmaf(av[i], wv[j], acc[i][j]);
        }
    }
    #pragma unroll
    for (int i = 0; i < 4; i++) {
        int r = rowBase + (ty << 2) + i;
        #pragma unroll
        for (int j = 0; j < 4; j++) {
            int c = colBase + (tx << 2) + j;
            float v = acc[i][j];
            if (bias) v += bias[c];
            if (act == 1) v = tanhf(v);
            C[(size_t)r * N + c] = v;
        }
    }
}

// ---------------- megakernel ----------------
struct MKArgs {
    const float *hs, *embed, *W1_W, *b1_W, *W1_Wx, *b1_Wx, *Wenc;
    const float *U1, *Ux1, *U2, *b2, *Wc, *Ux2, *bUx2, *Wcx;
    const float *Ws, *bs, *Wy, *We, *Wlogit, *blogit, *Wdec, *Winit, *binit;
    const int *hlens, *ys;
    float* out;
};

__global__ void __launch_bounds__(NTHR, 2) k_mega(MKArgs a) {
    extern __shared__ float SM[];
    float* abuf = SM;          // 2048 floats
    float* wbuf = SM + 2048;   // 8192 floats

    float* eys  = g_scratch + OFF_EYS;
    float* sb   = g_scratch + OFF_SB;
    float* sbx  = g_scratch + OFF_SBX;
    float* enc  = g_scratch + OFF_ENC;
    float* yw   = g_scratch + OFF_YW;
    float* hsum = g_scratch + OFF_HSUM;
    float* h    = g_scratch + OFF_H;
    float* h1   = g_scratch + OFF_H1;
    float* cvec = g_scratch + OFF_C;
    float* ym   = g_scratch + OFF_YM;
    float* l512 = g_scratch + OFF_L512;
    float* ms   = g_scratch + OFF_MS;
    float* expb = g_scratch + OFF_EXP;
    float* cp   = g_scratch + OFF_CP;
    float* ast  = g_scratch + OFF_AST;
    float* pA   = g_scratch + OFF_PA;
    float* pB   = g_scratch + OFF_PB;

    const int tid = threadIdx.x;
    const int bid = blockIdx.x;
    unsigned gen = 0;

    // ===== phase 0a: setup (ymask, eys gather, hsum) =====
    if (bid == 0 && tid < 32) {
        int b = tid;
        int yl = 0;
        for (int j = 0; j < 99; j++) yl += (a.ys[b * 99 + j] != -1) ? 1 : 0;
        for (int i = 0; i < 100; i++)
            ym[i * 32 + b] = (i < yl + 1) ? 1.f : 0.f;
    }
    for (int idx4 = bid * NTHR + tid; idx4 < 204800; idx4 += NBLK * NTHR) {
        int row = idx4 >> 6;
        int i = row >> 5, b = row & 31;
        int tok = 4999;
        if (i > 0) { int v = a.ys[b * 99 + i - 1]; tok = (v < 0) ? 4999 : v; }
        int c4 = (idx4 & 63) << 2;
        *(float4*)&eys[(size_t)row * 256 + c4] =
            *(const float4*)&a.embed[(size_t)tok * 256 + c4];
    }
    for (int t = bid; t < 256; t += NBLK) {
        int b = t >> 3, ech = t & 7;
        if (tid < 128) {
            int e = ech * 128 + tid;
            const float* base = a.hs + (size_t)b * 512000 + e;
            float s0 = 0.f, s1 = 0.f;
            for (int tt = 0; tt < 500; tt += 2) {
                s0 += __ldcs(base + (size_t)tt * 1024);
                s1 += __ldcs(base + (size_t)(tt + 1) * 1024);
            }
            hsum[b * 1024 + e] = (s0 + s1) / (float)a.hlens[b];
        }
    }
    gsync(gen);

    // ===== phase 0b: sb, sbx, yW, enc via 64x64 tiles (5200 tiles) =====
    for (int t = bid; t < 5200; t += NBLK) {
        if (t < 1600)       tiled64(eys, a.W1_W, a.b1_W, sb, 2048, 256, 0,
                                    t % 32, t / 32, SM);
        else if (t < 2400)  tiled64(eys, a.W1_Wx, a.b1_Wx, sbx, 1024, 256, 0,
                                    (t - 1600) % 16, (t - 1600) / 16, SM);
        else if (t < 3200)  tiled64(eys, a.Wy, nullptr, yw, 1024, 256, 0,
                                    (t - 2400) % 16, (t - 2400) / 16, SM);
        else                tiled64(a.hs, a.Wenc, nullptr, enc, 512, 1024, 1,
                                    (t - 3200) % 8, (t - 3200) / 8, SM);
    }
    gsync(gen);

    // ===== h0 = hsum @ Winit + binit : 128 tiles =====
    for (int t = bid; t < 128; t += NBLK) {
        int ct = t & 7, ks = t >> 3;
        GPair p = {hsum, 1024, a.Winit, 1024, 1024};
        gemm_tile(&p, 1, ks, 16, ct * 128, 128,
                  pA + (size_t)ks * 32768 + ct * 128, 1024, abuf, wbuf, 0);
    }
    gsync(gen);
    for (int idx = bid * NTHR + tid; idx < 32768; idx += NBLK * NTHR) {
        float s = a.binit[idx & 1023];
        #pragma unroll 4
        for (int sI = 0; sI < 16; sI++) s += pA[(size_t)sI * 32768 + idx];
        h[idx] = s;
    }
    // prefetch first P1 W tile (step 0)
    if (bid < 288) {
        int ct = bid % 24, ks = bid / 24;
        if (ct < 16) prefetchW(a.U1, 2048, ks * 32, ct * 128, 128, wbuf);
        else         prefetchW(a.Ux1, 1024, ks * 32, (ct - 16) * 128, 128, wbuf);
    }
    gsync(gen);

    for (int step = 0; step < 100; step++) {
        // ===== P1: fused 9b(step-1) + gate1 = [h@U1 | h@Ux1], 288 tiles =====
        if (step > 0) {
            for (int t = bid; t < 256; t += NBLK) {
                int b = t & 31, q = t >> 5;
                float gm = -1e30f;
                #pragma unroll
                for (int w = 0; w < 8; w++) gm = fmaxf(gm, ms[(b * 8 + w) * 2]);
                float gs = 0.f;
                #pragma unroll
                for (int w = 0; w < 8; w++)
                    gs += ms[(b * 8 + w) * 2 + 1] * expf(ms[(b * 8 + w) * 2] - gm);
                float scale = expf(ms[(b * 8 + q) * 2] - gm) / gs;
                float* o = a.out + (size_t)b * 500000 + (size_t)(step - 1) * 5000 + q * 625;
                const float* src = expb + (size_t)b * 5000 + q * 625;
                for (int j0 = tid; j0 < 625; j0 += NTHR) __stcs(o + j0, src[j0] * scale);
            }
        }
        for (int t = bid; t < 288; t += NBLK) {
            int ct = t % 24, ks = t / 24;      // KS=12
            if (ct < 16) {
                GPair p = {h, 1024, a.U1, 2048, 1024};
                gemm_tile(&p, 1, ks, 12, ct * 128, 128,
                          pA + (size_t)ks * 98304 + ct * 128, 3072, abuf, wbuf, 1);
            } else {
                GPair p = {h, 1024, a.Ux1, 1024, 1024};
                gemm_tile(&p, 1, ks, 12, (ct - 16) * 128, 128,
                          pA + (size_t)ks * 98304 + 2048 + (ct - 16) * 128, 3072,
                          abuf, wbuf, 1);
            }
        }
        gsync(gen);

        // ===== P2: ew1 (float4, 12-slot reduce) -> h1 =====
        for (int q = bid * NTHR + tid; q < 8192; q += NBLK * NTHR) {
            int r = q >> 8, j4 = (q & 255) << 2;
            float4 pr = {0,0,0,0}, uv = {0,0,0,0}, hx = {0,0,0,0};
            #pragma unroll
            for (int s = 0; s < 12; s++) {
                const float* P = pA + (size_t)s * 98304 + (size_t)r * 3072;
                float4 v;
                v = *(const float4*)(P + j4);        pr.x+=v.x; pr.y+=v.y; pr.z+=v.z; pr.w+=v.w;
                v = *(const float4*)(P + 1024 + j4); uv.x+=v.x; uv.y+=v.y; uv.z+=v.z; uv.w+=v.w;
                v = *(const float4*)(P + 2048 + j4); hx.x+=v.x; hx.y+=v.y; hx.z+=v.z; hx.w+=v.w;
            }
            const float* x_ = sb + (size_t)step * 65536 + (size_t)r * 2048;
            float4 xa = *(const float4*)(x_ + j4);
            float4 xb = *(const float4*)(x_ + 1024 + j4);
            float4 xc = *(const float4*)(sbx + (size_t)step * 32768 + r * 1024 + j4);
            float4 ho = *(const float4*)(h + r * 1024 + j4);
            float m = ym[step * 32 + r];
            float4 res;
            #define EW1(L) { \
                float p_ = sigm(pr.L + xa.L); \
                float u_ = sigm(uv.L + xb.L); \
                float t_ = tanhf(hx.L * p_ + xc.L); \
                res.L = m * (u_ * ho.L + (1.f - u_) * t_) + (1.f - m) * ho.L; }
            EW1(x) EW1(y) EW1(z) EW1(w)
            #undef EW1
            *(float4*)(h1 + r * 1024 + j4) = res;
        }
        // prefetch first P3 W tile
        if (bid < 280) {
            int t = bid;
            if (t < 40)       prefetchW(a.Wdec, 512, (t >> 2) * 32, (t & 3) * 128, 128, wbuf);
            else if (t < 200) { int tt = t - 40;
                                prefetchW(a.U2, 2048, (tt / 16) * 32, (tt % 16) * 128, 128, wbuf); }
            else              { int tt = t - 200;
                                prefetchW(a.Ux2, 1024, (tt >> 3) * 32, (tt & 7) * 128, 128, wbuf); }
        }
        gsync(gen);

        // ===== P3: dq + h1@U2 + h1@Ux2 partials, 280 tiles (KS=10) =====
        for (int t = bid; t < 280; t += NBLK) {
            if (t < 40) {
                int ct = t & 3, ks = t >> 2;
                GPair p = {h1, 1024, a.Wdec, 512, 1024};
                gemm_tile(&p, 1, ks, 10, ct * 128, 128,
                          pB + (size_t)ks * 16384 + ct * 128, 512, abuf, wbuf, 1);
            } else if (t < 200) {
                int tt = t - 40, ct = tt % 16, ks = tt / 16;
                GPair p = {h1, 1024, a.U2, 2048, 1024};
                gemm_tile(&p, 1, ks, 10, ct * 128, 128,
                          pA + (size_t)ks * 98304 + ct * 128, 3072, abuf, wbuf, 1);
            } else {
                int tt = t - 200, ct = tt & 7, ks = tt >> 3;
                GPair p = {h1, 1024, a.Ux2, 1024, 1024};
                gemm_tile(&p, 1, ks, 10, ct * 128, 128,
                          pA + (size_t)ks * 98304 + 2048 + ct * 128, 3072, abuf, wbuf, 1);
            }
        }
        gsync(gen);

        // ===== P4: online-softmax attention, 288 tiles (b x 9 t-chunks of 56) =====
        for (int t = bid; t < 288; t += NBLK) {
            int b = t & 31, tch = t >> 5;
            __syncthreads();
            float* dqs = SM;           // 512
            float* sc  = SM + 512;     // 56
            for (int j = tid; j < 512; j += NTHR) {
                float s = 0.f;
                #pragma unroll
                for (int sI = 0; sI < 10; sI++)
                    s += pB[(size_t)sI * 16384 + b * 512 + j];
                dqs[j] = tanhf(s);
            }
            __syncthreads();
            int t0 = tch * 56;
            int tn = 500 - t0; if (tn > 56) tn = 56;
            int w = tid >> 5, l = tid & 31;
            int hl = a.hlens[b];
            for (int tt = w; tt < tn; tt += 8) {
                const float* row = enc + ((size_t)b * 500 + t0 + tt) * 512;
                float s = 0.f;
                #pragma unroll
                for (int qq = 0; qq < 16; qq++)
                    s = fmaf(row[l + qq * 32], dqs[l + qq * 32], s);
                #pragma unroll
                for (int o = 16; o; o >>= 1) s += __shfl_xor_sync(0xffffffffu, s, o);
                if (l == 0) sc[tt] = (t0 + tt < hl) ? s : -1e9f;
            }
            __syncthreads();
            if (tid < 32) {
                float mloc = -1e30f;
                for (int i = l; i < tn; i += 32) mloc = fmaxf(mloc, sc[i]);
                #pragma unroll
                for (int o = 16; o; o >>= 1) mloc = fmaxf(mloc, __shfl_xor_sync(0xffffffffu, mloc, o));
                float ssum = 0.f;
                for (int i = l; i < tn; i += 32) {
                    float e = expf(sc[i] - mloc);
                    sc[i] = e;
                    ssum += e;
                }
                #pragma unroll
                for (int o = 16; o; o >>= 1) ssum += __shfl_xor_sync(0xffffffffu, ssum, o);
                if (l == 0) {
                    ast[(b * 9 + tch) * 2]     = mloc;
                    ast[(b * 9 + tch) * 2 + 1] = ssum;
                }
            }
            __syncthreads();
            // ctx partial: 256 threads x 4 e-cols, hs streamed evict-first
            int e0 = tid * 4;
            float4 acc = {0,0,0,0};
            const float* hb = a.hs + (size_t)b * 512000 + (size_t)t0 * 1024 + e0;
            for (int tt = 0; tt < tn; tt++) {
                float wg = sc[tt];
                float4 hv = __ldcs((const float4*)(hb + (size_t)tt * 1024));
                acc.x = fmaf(wg, hv.x, acc.x);
                acc.y = fmaf(wg, hv.y, acc.y);
                acc.z = fmaf(wg, hv.z, acc.z);
                acc.w = fmaf(wg, hv.w, acc.w);
            }
            *(float4*)(cp + (size_t)(b * 9 + tch) * 1024 + e0) = acc;
            __syncthreads();
        }
        gsync(gen);

        // ===== P5: ctx combine -> cvec, 128 tiles (b x 4 e-chunks of 256) =====
        for (int t = bid; t < 128; t += NBLK) {
            int b = t & 31, ech = t >> 5;
            float M = -1e30f;
            #pragma unroll
            for (int ch = 0; ch < 9; ch++) M = fmaxf(M, ast[(b * 9 + ch) * 2]);
            float Z = 0.f;
            float scl[9];
            #pragma unroll
            for (int ch = 0; ch < 9; ch++) {
                scl[ch] = expf(ast[(b * 9 + ch) * 2] - M);
                Z += ast[(b * 9 + ch) * 2 + 1] * scl[ch];
            }
            float inv = 1.f / Z;
            int e = ech * 256 + tid;
            float s = 0.f;
            #pragma unroll
            for (int ch = 0; ch < 9; ch++)
                s = fmaf(cp[(size_t)(b * 9 + ch) * 1024 + e], scl[ch], s);
            cvec[b * 1024 + e] = s * inv;
        }
        // prefetch first P6 W tile
        if (bid < 288) {
            int t = bid;
            if (t < 144)      prefetchW(a.Wc, 2048, (t / 16) * 32, (t % 16) * 128, 128, wbuf);
            else if (t < 216) { int tt = t - 144;
                                prefetchW(a.Wcx, 1024, (tt >> 3) * 32, (tt & 7) * 128, 128, wbuf); }
            else              { int tt = t - 216;
                                prefetchW(a.We, 1024, (tt >> 3) * 32, (tt & 7) * 128, 128, wbuf); }
        }
        gsync(gen);

        // ===== P6: c@Wc | c@Wcx | c@We, 288 tiles (KS=9) =====
        for (int t = bid; t < 288; t += NBLK) {
            if (t < 144) {
                int ct = t % 16, ks = t / 16;
                GPair p = {cvec, 1024, a.Wc, 2048, 1024};
                gemm_tile(&p, 1, ks, 9, ct * 128, 128,
                          pB + (size_t)ks * 131072 + ct * 128, 4096, abuf, wbuf, 1);
            } else if (t < 216) {
                int tt = t - 144, ct = tt & 7, ks = tt >> 3;
                GPair p = {cvec, 1024, a.Wcx, 1024, 1024};
                gemm_tile(&p, 1, ks, 9, ct * 128, 128,
                          pB + (size_t)ks * 131072 + 2048 + ct * 128, 4096, abuf, wbuf, 1);
            } else {
                int tt = t - 216, ct = tt & 7, ks = tt >> 3;
                GPair p = {cvec, 1024, a.We, 1024, 1024};
                gemm_tile(&p, 1, ks, 9, ct * 128, 128,
                          pB + (size_t)ks * 131072 + 3072 + ct * 128, 4096, abuf, wbuf, 1);
            }
        }
        gsync(gen);

        // ===== P7: ew2 (float4) -> h (=h2) =====
        for (int q = bid * NTHR + tid; q < 8192; q += NBLK * NTHR) {
            int r = q >> 8, j4 = (q & 255) << 2;
            float4 pr = {0,0,0,0}, uv = {0,0,0,0}, hx = {0,0,0,0}, cx = {0,0,0,0};
            #pragma unroll
            for (int s = 0; s < 10; s++) {
                const float* P = pA + (size_t)s * 98304 + (size_t)r * 3072;
                float4 v;
                v = *(const float4*)(P + j4);        pr.x+=v.x; pr.y+=v.y; pr.z+=v.z; pr.w+=v.w;
                v = *(const float4*)(P + 1024 + j4); uv.x+=v.x; uv.y+=v.y; uv.z+=v.z; uv.w+=v.w;
                v = *(const float4*)(P + 2048 + j4); hx.x+=v.x; hx.y+=v.y; hx.z+=v.z; hx.w+=v.w;
            }
            #pragma unroll
            for (int s = 0; s < 9; s++) {
                const float* P = pB + (size_t)s * 131072 + (size_t)r * 4096;
                float4 v;
                v = *(const float4*)(P + j4);        pr.x+=v.x; pr.y+=v.y; pr.z+=v.z; pr.w+=v.w;
                v = *(const float4*)(P + 1024 + j4); uv.x+=v.x; uv.y+=v.y; uv.z+=v.z; uv.w+=v.w;
                v = *(const float4*)(P + 2048 + j4); cx.x+=v.x; cx.y+=v.y; cx.z+=v.z; cx.w+=v.w;
            }
            float4 ba = *(const float4*)(a.b2 + j4);
            float4 bb = *(const float4*)(a.b2 + 1024 + j4);
            float4 bu = *(const float4*)(a.bUx2 + j4);
            float4 h1v = *(const float4*)(h1 + r * 1024 + j4);
            float m = ym[step * 32 + r];
            float4 res;
            #define EW2(L) { \
                float p_ = sigm(pr.L + ba.L); \
                float u_ = sigm(uv.L + bb.L); \
                float t_ = tanhf((hx.L + bu.L) * p_ + cx.L); \
                res.L = m * (u_ * h1v.L + (1.f - u_) * t_) + (1.f - m) * h1v.L; }
            EW2(x) EW2(y) EW2(z) EW2(w)
            #undef EW2
            *(float4*)(h + r * 1024 + j4) = res;
        }
        // prefetch P8 W tile (m=1 phase: removes its whole load exposure)
        if (bid < 256)
            prefetchW(a.Ws, 1024, (bid >> 3) * 32, (bid & 7) * 128, 128, wbuf);
        gsync(gen);

        // ===== P8: h2@Ws, 256 tiles (KS=32, m=1, W prefetched) =====
        for (int t = bid; t < 256; t += NBLK) {
            int ct = t & 7, ks = t >> 3;
            GPair p = {h, 1024, a.Ws, 1024, 1024};
            gemm_tile(&p, 1, ks, 32, ct * 128, 128,
                      pA + (size_t)ks * 32768 + ct * 128, 1024, abuf, wbuf, 1);
        }
        gsync(gen);

        // ===== P9: pool (32 Ws slots + 9 We slots + yW + bs, pairmax) -> l512 =====
        for (int idx = bid * NTHR + tid; idx < 16384; idx += NBLK * NTHR) {
            int r = idx >> 9, p2 = idx & 511;
            float2 v = *(const float2*)(a.bs + 2 * p2);
            float2 yv = *(const float2*)(yw + (size_t)step * 32768 + r * 1024 + 2 * p2);
            v.x += yv.x; v.y += yv.y;
            #pragma unroll 8
            for (int s = 0; s < 32; s++) {
                float2 pv = *(const float2*)(pA + (size_t)s * 32768 + (size_t)r * 1024 + 2 * p2);
                v.x += pv.x; v.y += pv.y;
            }
            #pragma unroll
            for (int s = 0; s < 9; s++) {
                float2 pv = *(const float2*)(pB + (size_t)s * 131072 + (size_t)r * 4096 + 3072 + 2 * p2);
                v.x += pv.x; v.y += pv.y;
            }
            l512[idx] = fmaxf(v.x, v.y);
        }
        // prefetch first P10 W tile
        if (bid < 280) {
            int ct = bid % 40, ks = bid / 40;
            int nc = 5000 - ct * 128; if (nc > 128) nc = 128;
            prefetchW(a.Wlogit, 5000, ks * 32, ct * 128, nc, wbuf);
        }
        gsync(gen);

        // ===== P10: logits5000 = l512 @ Wlogit, 280 tiles (KS=7) =====
        for (int t = bid; t < 280; t += NBLK) {
            int ct = t % 40, ks = t / 40;
            int ncols = 5000 - ct * 128; if (ncols > 128) ncols = 128;
            GPair p = {l512, 512, a.Wlogit, 5000, 512};
            gemm_tile(&p, 1, ks, 7, ct * 128, ncols,
                      pA + (size_t)ks * 160000 + ct * 128, 5000, abuf, wbuf, 1);
        }
        gsync(gen);

        // ===== P11: reduce 7 partials + local max + exp, 256 tiles =====
        for (int t = bid; t < 256; t += NBLK) {
            int b = t & 31, q = t >> 5;
            float* buf = SM;
            float* red = SM + 640;
            __syncthreads();
            float lm = -1e30f;
            for (int j0 = tid; j0 < 625; j0 += NTHR) {
                int j = q * 625 + j0;
                float v = a.blogit[j];
                #pragma unroll
                for (int s = 0; s < 7; s++)
                    v += pA[(size_t)s * 160000 + (size_t)b * 5000 + j];
                buf[j0] = v;
                lm = fmaxf(lm, v);
            }
            #pragma unroll
            for (int o = 16; o; o >>= 1) lm = fmaxf(lm, __shfl_xor_sync(0xffffffffu, lm, o));
            if ((tid & 31) == 0) red[tid >> 5] = lm;
            __syncthreads();
            float gml = red[0];
            #pragma unroll
            for (int w = 1; w < 8; w++) gml = fmaxf(gml, red[w]);
            float ls = 0.f;
            for (int j0 = tid; j0 < 625; j0 += NTHR) {
                float e = expf(buf[j0] - gml);
                expb[(size_t)b * 5000 + q * 625 + j0] = e;
                ls += e;
            }
            #pragma unroll
            for (int o = 16; o; o >>= 1) ls += __shfl_xor_sync(0xffffffffu, ls, o);
            __syncthreads();
            if ((tid & 31) == 0) red[tid >> 5] = ls;
            __syncthreads();
            if (tid == 0) {
                float tot = 0.f;
                #pragma unroll
                for (int w = 0; w < 8; w++) tot += red[w];
                ms[(b * 8 + q) * 2]     = gml;
                ms[(b * 8 + q) * 2 + 1] = tot;
            }
            __syncthreads();
        }
        // prefetch first W tile of next step's P1
        if (bid < 288) {
            int ct = bid % 24, ks = bid / 24;
            if (ct < 16) prefetchW(a.U1, 2048, ks * 32, ct * 128, 128, wbuf);
            else         prefetchW(a.Ux1, 1024, ks * 32, (ct - 16) * 128, 128, wbuf);
        }
        gsync(gen);
    }

    // ===== final 9b for step 99 =====
    for (int t = bid; t < 256; t += NBLK) {
        int b = t & 31, q = t >> 5;
        float gm = -1e30f;
        #pragma unroll
        for (int w = 0; w < 8; w++) gm = fmaxf(gm, ms[(b * 8 + w) * 2]);
        float gs = 0.f;
        #pragma unroll
        for (int w = 0; w < 8; w++)
            gs += ms[(b * 8 + w) * 2 + 1] * expf(ms[(b * 8 + w) * 2] - gm);
        float scale = expf(ms[(b * 8 + q) * 2] - gm) / gs;
        float* o = a.out + (size_t)b * 500000 + (size_t)99 * 5000 + q * 625;
        const float* src = expb + (size_t)b * 5000 + q * 625;
        for (int j0 = tid; j0 < 625; j0 += NTHR) __stcs(o + j0, src[j0] * scale);
    }

    // ===== safe barrier-counter reset =====
    __syncthreads();
    if (tid == 0) {
        unsigned r;
        asm volatile("atom.acq_rel.gpu.global.add.u32 %0, [%1], 1;"
                     : "=r"(r) : "l"(&g_bar_cnt2) : "memory");
        if (r == NBLK - 1) {
            g_bar_cnt = 0;
            g_bar_cnt2 = 0;
            __threadfence();
        }
    }
}

// ---------------- host launcher: single kernel ----------------
extern "C" void kernel_launch(void* const* d_in, const int* in_sizes, int n_in,
                              void* d_out, int out_size) {
    MKArgs a;
    a.hs     = (const float*)d_in[0];
    a.hlens  = (const int*)  d_in[1];
    a.ys     = (const int*)  d_in[2];
    a.embed  = (const float*)d_in[3];
    a.W1_W   = (const float*)d_in[4];
    a.b1_W   = (const float*)d_in[5];
    a.W1_Wx  = (const float*)d_in[6];
    a.b1_Wx  = (const float*)d_in[7];
    a.U1     = (const float*)d_in[8];
    a.Ux1    = (const float*)d_in[9];
    a.U2     = (const float*)d_in[10];
    a.b2     = (const float*)d_in[11];
    a.Wc     = (const float*)d_in[12];
    a.Ux2    = (const float*)d_in[13];
    a.bUx2   = (const float*)d_in[14];
    a.Wcx    = (const float*)d_in[15];
    a.Winit  = (const float*)d_in[16];
    a.binit  = (const float*)d_in[17];
    a.Ws     = (const float*)d_in[18];
    a.bs     = (const float*)d_in[19];
    a.Wy     = (const float*)d_in[20];
    a.We     = (const float*)d_in[21];
    a.Wlogit = (const float*)d_in[22];
    a.blogit = (const float*)d_in[23];
    a.Wenc   = (const float*)d_in[24];
    a.Wdec   = (const float*)d_in[25];
    a.out    = (float*)d_out;

    cudaFuncSetAttribute(k_mega, cudaFuncAttributeMaxDynamicSharedMemorySize, 40960);
    k_mega<<<NBLK, NTHR, 40960>>>(a);
}